// round 10
// baseline (speedup 1.0000x reference)
#include <cuda_runtime.h>
#include <cuda_fp16.h>

#define BSZ 1024
#define T1  127
#define TP  128
#define HD  128
#define HE  128
#define ZD  512
#define GMAX 7
#define NCTA 147
#define THREADS 1024
#define ZPB 520
#define ZPH (7*ZPB)

__device__ __half g_prex[(size_t)BSZ * TP * HE];   // 33.5 MB
__device__ float  g_px2[BSZ * T1];
__device__ __half g_whh[HD * ZD];

static __device__ __forceinline__ float tanh_ap(float x){
    float r; asm("tanh.approx.f32 %0, %1;" : "=f"(r) : "f"(x)); return r;
}
static __device__ __forceinline__ float sig_ap(float x){
    return fmaf(0.5f, tanh_ap(0.5f * x), 0.5f);
}
static __device__ __forceinline__ unsigned tanh2_ap(unsigned x){
    unsigned r; asm("tanh.approx.f16x2 %0, %1;" : "=r"(r) : "r"(x)); return r;
}
static __device__ __forceinline__ unsigned h2u(__half2 h){
    union { __half2 h; unsigned u; } v; v.h = h; return v.u;
}
static __device__ __forceinline__ __half2 u2h(unsigned u){
    union { __half2 h; unsigned u; } v; v.u = u; return v.h;
}

#define FMA2(d,a,b,c)  asm("fma.rn.f32x2 %0, %1, %2, %3;" : "=l"(d) : "l"(a), "l"(b), "l"(c))
#define PACKB(d,x)     asm("mov.b64 %0, {%1,%1};" : "=l"(d) : "f"(x))
#define PACK2(d,x,y)   asm("mov.b64 %0, {%1,%2};" : "=l"(d) : "f"(x), "f"(y))
#define UNPACK2(x,y,d) asm("mov.b64 {%0,%1}, %2;" : "=f"(x), "=f"(y) : "l"(d))

#define BARS(id, n) asm volatile("bar.sync %0, %1;" :: "r"(id), "r"(n) : "memory")
#define BARA(id, n) asm volatile("bar.arrive %0, %1;" :: "r"(id), "r"(n) : "memory")

#define CP16(dst_u32, src_ptr) \
    asm volatile("cp.async.cg.shared.global [%0], [%1], 16;" :: "r"(dst_u32), "l"(src_ptr) : "memory")
#define CP_COMMIT() asm volatile("cp.async.commit_group;" ::: "memory")
#define CP_WAIT2()  asm volatile("cp.async.wait_group 2;" ::: "memory")

// ---------------------------------------------------------------------------
// Prepass (+ Wh -> fp16 in blocks 0..255)
// ---------------------------------------------------------------------------
#define PRE_SMEM ((HD*HE + T1*HE) * 4)

__global__ void __launch_bounds__(256, 1)
prex_kernel(const float* __restrict__ X, const float* __restrict__ W1,
            const float* __restrict__ b1, const float* __restrict__ Wfc,
            const float* __restrict__ Wh)
{
    extern __shared__ float sm[];
    float* sW = sm;
    float* sX = sm + HD * HE;
    int b = blockIdx.x;
    int tid = threadIdx.x, lane = tid & 31, wid = tid >> 5;
    const float* Xb = X + (size_t)b * T1 * HE;

    if (b < 256) g_whh[b * 256 + tid] = __float2half(Wh[b * 256 + tid]);

    for (int i = tid; i < HD * HE; i += 256) sW[i] = W1[2 * HD * HE + i];
    for (int i = tid; i < T1 * HE; i += 256) sX[i] = Xb[i];
    __syncthreads();

    int e = tid & 127, th = tid >> 7;
    float b1e = b1[e];
    for (int t = th; t < T1; t += 2) {
        float acc = 0.f;
        const float* xr = sX + t * HE;
        #pragma unroll 8
        for (int k = 0; k < HE; k++) acc = fmaf(xr[k], sW[k * HE + e], acc);
        g_prex[((size_t)b * TP + t) * HE + e] = __float2half(acc + b1e);
    }
    if (tid < 128) g_prex[((size_t)b * TP + 127) * HE + tid] = __float2half(0.f);

    float4 wf = ((const float4*)Wfc)[lane];
    for (int t = wid; t < T1; t += 8) {
        float4 x = ((const float4*)(sX + t * HE))[lane];
        float p = x.x * wf.x + x.y * wf.y + x.z * wf.z + x.w * wf.w;
        #pragma unroll
        for (int m = 16; m; m >>= 1) p += __shfl_xor_sync(0xffffffffu, p, m);
        if (lane == 0) g_px2[b * T1 + t] = p;
    }
}

// ---------------------------------------------------------------------------
// Main kernel: 147 CTAs x 7 batches x 1024 threads, warp-specialized
// ---------------------------------------------------------------------------
#define O_W1H  0
#define O_VA   16384
#define O_ZP   (O_VA + 3584)
#define O_D    (O_ZP + 14560)
#define O_C    (O_D + 1024)
#define O_BETA (O_C + 1024)
#define O_PX2  (O_BETA + 896)
#define O_YP   (O_PX2 + 896)
#define O_W2   (O_YP + 896)
#define O_WX   (O_W2 + 128)
#define O_BL   (O_WX + 512)
#define O_SSB  (O_BL + 512)
#define O_SQ   (O_SSB + 16)
#define O_RING (O_SQ + 8)             // 14 warps x 1024 floats (4KB ring each)
#define MAIN_FLOATS (O_RING + 14*1024)
#define MAIN_SMEM (MAIN_FLOATS * 4)   // 219,104 B

struct Ctx {
    __half2* sW1h; float* sva; float* szp; float* sd; float* sc; float* sbeta;
    float* spx2; float* syp; float* sW2; float* sWx; float* sbl; float* ssb; float* sq;
};

// Phase B with cp.async ring (3 chunks of 4 tp in flight)
static __device__ __forceinline__ void phaseB(const Ctx& cx, float* ringw,
                                              int b0, int b, int half_,
                                              int lane, bool last, float b2v)
{
    float4 vr = make_float4(0.f, 0.f, 0.f, 0.f);
    #pragma unroll
    for (int h = 0; h < 4; h++) {
        float4 a = ((const float4*)(cx.sva + h*896 + b*128))[lane];
        vr.x += a.x; vr.y += a.y; vr.z += a.z; vr.w += a.w;
    }
    float4 w2r = ((const float4*)cx.sW2)[lane];
    __half2 vr01 = __floats2half2_rn(vr.x, vr.y);
    __half2 vr23 = __floats2half2_rn(vr.z, vr.w);
    __half2 w01  = __floats2half2_rn(w2r.x, w2r.y);
    __half2 w23  = __floats2half2_rn(w2r.z, w2r.w);

    const char* gsrc = (const char*)(g_prex + (size_t)(b0 + b) * TP * HE + half_ * 64 * HE);
    unsigned rb = (unsigned)__cvta_generic_to_shared(ringw);
    const float* px2b = cx.spx2 + b * 128;
    int tp0 = half_ * 64;
    float s_l = 0.f;

    // prologue: 3 chunks in flight
    #pragma unroll
    for (int i = 0; i < 3; i++) {
        unsigned dst = rb + i * 1024 + lane * 16;
        const char* src = gsrc + i * 1024 + lane * 16;
        CP16(dst, src);
        CP16(dst + 512, src + 512);
        CP_COMMIT();
    }

    #pragma unroll 1
    for (int i = 0; i < 16; i++) {
        CP_WAIT2();
        __syncwarp();
        const float* slot = ringw + (i & 3) * 256 + lane * 2;
        uint2 c0 = *(const uint2*)(slot);
        uint2 c1 = *(const uint2*)(slot + 64);
        uint2 c2 = *(const uint2*)(slot + 128);
        uint2 c3 = *(const uint2*)(slot + 192);
        if (i + 3 < 16) {
            unsigned dst = rb + ((i + 3) & 3) * 1024 + lane * 16;
            const char* src = gsrc + (i + 3) * 1024 + lane * 16;
            CP16(dst, src);
            CP16(dst + 512, src + 512);
            CP_COMMIT();
        }

        __half2 h0a = u2h(tanh2_ap(h2u(__hadd2(u2h(c0.x), vr01))));
        __half2 h0b = u2h(tanh2_ap(h2u(__hadd2(u2h(c0.y), vr23))));
        __half2 h1a = u2h(tanh2_ap(h2u(__hadd2(u2h(c1.x), vr01))));
        __half2 h1b = u2h(tanh2_ap(h2u(__hadd2(u2h(c1.y), vr23))));
        __half2 h2a = u2h(tanh2_ap(h2u(__hadd2(u2h(c2.x), vr01))));
        __half2 h2b = u2h(tanh2_ap(h2u(__hadd2(u2h(c2.y), vr23))));
        __half2 h3a = u2h(tanh2_ap(h2u(__hadd2(u2h(c3.x), vr01))));
        __half2 h3b = u2h(tanh2_ap(h2u(__hadd2(u2h(c3.y), vr23))));

        __half2 p0 = __hfma2(h0b, w23, __hmul2(h0a, w01));
        __half2 p1 = __hfma2(h1b, w23, __hmul2(h1a, w01));
        __half2 p2 = __hfma2(h2b, w23, __hmul2(h2a, w01));
        __half2 p3 = __hfma2(h3b, w23, __hmul2(h3a, w01));
        float2 q0 = __half22float2(p0);
        float2 q1 = __half22float2(p1);
        float2 q2 = __half22float2(p2);
        float2 q3 = __half22float2(p3);
        float pl0 = q0.x + q0.y, pl1 = q1.x + q1.y;
        float pl2 = q2.x + q2.y, pl3 = q3.x + q3.y;

        int tp = tp0 + i * 4;
        s_l = fmaf(pl0, px2b[tp+0], s_l);
        s_l = fmaf(pl1, px2b[tp+1], s_l);
        s_l = fmaf(pl2, px2b[tp+2], s_l);
        s_l = fmaf(pl3, px2b[tp+3], s_l);

        if (last) {
            float r0 = pl0, r1 = pl1, r2 = pl2, r3 = pl3;
            #pragma unroll
            for (int m = 16; m; m >>= 1) {
                r0 += __shfl_xor_sync(0xffffffffu, r0, m);
                r1 += __shfl_xor_sync(0xffffffffu, r1, m);
                r2 += __shfl_xor_sync(0xffffffffu, r2, m);
                r3 += __shfl_xor_sync(0xffffffffu, r3, m);
            }
            if (lane == 0) {
                cx.sbeta[b*128 + tp+0] = r0 + b2v;
                cx.sbeta[b*128 + tp+1] = r1 + b2v;
                cx.sbeta[b*128 + tp+2] = r2 + b2v;
                cx.sbeta[b*128 + tp+3] = r3 + b2v;
            }
        }
    }
    #pragma unroll
    for (int m = 16; m; m >>= 1) s_l += __shfl_xor_sync(0xffffffffu, s_l, m);
    if (lane == 0) cx.ssb[2*b + half_] = s_l;
}

// Phase C: zp = d @ Wh, group2 (512 threads), transposed state, f32x2
static __device__ __forceinline__ void phaseC(const Ctx& cx, int tid2)
{
    int jg = tid2 & 127, h = tid2 >> 7, kb = h * 32;
    const __half* whp = g_whh + (size_t)kb * ZD + jg * 4;
    unsigned long long a01[GMAX], a23[GMAX];
    #pragma unroll
    for (int b = 0; b < GMAX; b++) { a01[b] = 0ULL; a23[b] = 0ULL; }

    uint2 wc0 = *(const uint2*)(whp + 0*ZD);
    uint2 wc1 = *(const uint2*)(whp + 1*ZD);
    uint2 wc2 = *(const uint2*)(whp + 2*ZD);
    uint2 wc3 = *(const uint2*)(whp + 3*ZD);

#define CROW(WREG, KROW) do { \
    float2 lo_ = __half22float2(u2h((WREG).x)); \
    float2 hi_ = __half22float2(u2h((WREG).y)); \
    unsigned long long w01_, w23_; \
    PACK2(w01_, lo_.x, lo_.y); PACK2(w23_, hi_.x, hi_.y); \
    float4 dA_ = *(const float4*)(cx.sd + (KROW)*8); \
    float4 dB_ = *(const float4*)(cx.sd + (KROW)*8 + 4); \
    unsigned long long dd_; \
    PACKB(dd_, dA_.x); FMA2(a01[0], dd_, w01_, a01[0]); FMA2(a23[0], dd_, w23_, a23[0]); \
    PACKB(dd_, dA_.y); FMA2(a01[1], dd_, w01_, a01[1]); FMA2(a23[1], dd_, w23_, a23[1]); \
    PACKB(dd_, dA_.z); FMA2(a01[2], dd_, w01_, a01[2]); FMA2(a23[2], dd_, w23_, a23[2]); \
    PACKB(dd_, dA_.w); FMA2(a01[3], dd_, w01_, a01[3]); FMA2(a23[3], dd_, w23_, a23[3]); \
    PACKB(dd_, dB_.x); FMA2(a01[4], dd_, w01_, a01[4]); FMA2(a23[4], dd_, w23_, a23[4]); \
    PACKB(dd_, dB_.y); FMA2(a01[5], dd_, w01_, a01[5]); FMA2(a23[5], dd_, w23_, a23[5]); \
    PACKB(dd_, dB_.z); FMA2(a01[6], dd_, w01_, a01[6]); FMA2(a23[6], dd_, w23_, a23[6]); \
} while(0)

    #pragma unroll 1
    for (int kk = 0; kk < 32; kk += 4) {
        int kn = (kk + 4 < 32) ? kk + 4 : kk;
        uint2 n0 = *(const uint2*)(whp + (size_t)(kn+0)*ZD);
        uint2 n1 = *(const uint2*)(whp + (size_t)(kn+1)*ZD);
        uint2 n2 = *(const uint2*)(whp + (size_t)(kn+2)*ZD);
        uint2 n3 = *(const uint2*)(whp + (size_t)(kn+3)*ZD);
        CROW(wc0, kb+kk+0);
        CROW(wc1, kb+kk+1);
        CROW(wc2, kb+kk+2);
        CROW(wc3, kb+kk+3);
        wc0 = n0; wc1 = n1; wc2 = n2; wc3 = n3;
    }
#undef CROW
    #pragma unroll
    for (int b = 0; b < GMAX; b++) {
        float* p = cx.szp + h*ZPH + b*ZPB + jg*4;
        *(unsigned long long*)p       = a01[b];
        *(unsigned long long*)(p + 2) = a23[b];
    }
}

__global__ void __launch_bounds__(THREADS, 1)
decoder_kernel(const float* __restrict__ X, const float* __restrict__ yprev,
               const float* __restrict__ W1, const float* __restrict__ W2,
               const float* __restrict__ b2, const float* __restrict__ Wfc,
               const float* __restrict__ bfc, const float* __restrict__ Wx,
               const float* __restrict__ Wh, const float* __restrict__ bl,
               const float* __restrict__ Wf, const float* __restrict__ bf,
               float* __restrict__ out)
{
    extern __shared__ float sm[];
    Ctx cx;
    cx.sW1h = (__half2*)(sm + O_W1H);
    cx.sva = sm + O_VA;  cx.szp = sm + O_ZP;
    cx.sd = sm + O_D;    cx.sc = sm + O_C;    cx.sbeta = sm + O_BETA;
    cx.spx2 = sm + O_PX2; cx.syp = sm + O_YP; cx.sW2 = sm + O_W2;
    cx.sWx = sm + O_WX;  cx.sbl = sm + O_BL;  cx.ssb = sm + O_SSB; cx.sq = sm + O_SQ;
    float* sring = sm + O_RING;

    int tid = threadIdx.x, lane = tid & 31, wid = tid >> 5;
    int b0 = blockIdx.x * GMAX;
    if (b0 >= BSZ) return;
    int nb = min(GMAX, BSZ - b0);

    for (int i = tid; i < HD * HE; i += THREADS)
        cx.sW1h[i] = __floats2half2_rn(W1[i], W1[HD * HE + i]);
    if (tid < 128) cx.sW2[tid] = W2[tid];
    if (tid < 512) { cx.sWx[tid] = Wx[tid]; cx.sbl[tid] = bl[tid]; }
    if (tid < 16) cx.ssb[tid] = 0.f;
    if (tid >= 16 && tid < 24) cx.sq[tid - 16] = 0.f;
    if (tid < GMAX * 128) {
        int b = tid >> 7, tp = tid & 127;
        bool ok = (b < nb) && (tp < T1);
        cx.spx2[tid] = ok ? g_px2[(b0 + b) * T1 + tp] : 0.f;
        cx.syp[tid]  = ok ? yprev[(size_t)(b0 + b) * T1 + tp] : 0.f;
    }
    {
        int b = tid & 7;
        float x00 = (b < nb) ? X[(size_t)(b0 + b) * T1 * HE] : 0.f;
        cx.sd[tid] = x00; cx.sc[tid] = x00;
    }
    float b2v  = b2[0];
    float bfcv = bfc[0];
    float wfcy = Wfc[HE];
    __syncthreads();
    if (wid < nb) {
        const float* p = cx.spx2 + wid * 128;
        float v = p[lane] + p[lane+32] + p[lane+64] + p[lane+96];
        #pragma unroll
        for (int m = 16; m; m >>= 1) v += __shfl_xor_sync(0xffffffffu, v, m);
        if (lane == 0) cx.sq[wid] = v;
    }
    __syncthreads();

    if (wid < 16) {
        // ========== GROUP 1: A then B ==========
        int e = tid & 127, h = tid >> 7, kb = h * 32;
        float* ringw = sring + wid * 1024;
        for (int t = 0; t < T1; t++) {
            if (t > 0) BARS(2, 1024);
            // ---- Phase A: f32x2 over batch pairs ----
            {
                unsigned long long acc0 = 0, acc1 = 0, acc2 = 0, acc3 = 0;
                const __half2* wrow = cx.sW1h + e;
                #pragma unroll 4
                for (int kk = 0; kk < 32; kk++) {
                    int k = kb + kk;
                    float2 w = __half22float2(wrow[k * 128]);
                    unsigned long long wd, wc_;
                    PACKB(wd, w.x); PACKB(wc_, w.y);
                    ulonglong2 dA = *(const ulonglong2*)(cx.sd + k*8);
                    ulonglong2 dB = *(const ulonglong2*)(cx.sd + k*8 + 4);
                    ulonglong2 cA = *(const ulonglong2*)(cx.sc + k*8);
                    ulonglong2 cB = *(const ulonglong2*)(cx.sc + k*8 + 4);
                    FMA2(acc0, dA.x, wd, acc0); FMA2(acc0, cA.x, wc_, acc0);
                    FMA2(acc1, dA.y, wd, acc1); FMA2(acc1, cA.y, wc_, acc1);
                    FMA2(acc2, dB.x, wd, acc2); FMA2(acc2, cB.x, wc_, acc2);
                    FMA2(acc3, dB.y, wd, acc3); FMA2(acc3, cB.y, wc_, acc3);
                }
                float* va = cx.sva + h * 896 + e;
                float v0, v1;
                UNPACK2(v0, v1, acc0); va[0]     = v0; va[128]   = v1;
                UNPACK2(v0, v1, acc1); va[256]   = v0; va[384]   = v1;
                UNPACK2(v0, v1, acc2); va[512]   = v0; va[640]   = v1;
                UNPACK2(v0, v1, acc3); va[768]   = v0;
            }
            BARS(3, 512);
            if (wid < 14) {
                int b = wid >> 1;
                if (b < nb) phaseB(cx, ringw, b0, b, wid & 1, lane, t == T1 - 1, b2v);
            }
            __threadfence_block();
            BARA(1, 1024);
        }
    } else {
        // ========== GROUP 2: C then D ==========
        int tid2 = tid - 512;
        for (int t = 0; t < T1; t++) {
            phaseC(cx, tid2);
            BARS(1, 1024);
            #pragma unroll
            for (int rep = 0; rep < 2; rep++) {
                int i = tid2 + rep * 512;
                int b = i & 7, k = i >> 3;
                float dn = 0.f, cn = 0.f;
                if (b < GMAX) {
                    float s  = cx.ssb[2*b] + cx.ssb[2*b+1] + b2v * cx.sq[b];
                    float yt = fmaf(cx.syp[b*128 + t], wfcy, s + bfcv);
                    const float* zb = cx.szp + b * ZPB;
                    float zi = zb[k]       + zb[ZPH + k]       + zb[2*ZPH + k]       + zb[3*ZPH + k];
                    float zf = zb[128 + k] + zb[ZPH + 128 + k] + zb[2*ZPH + 128 + k] + zb[3*ZPH + 128 + k];
                    float zg = zb[256 + k] + zb[ZPH + 256 + k] + zb[2*ZPH + 256 + k] + zb[3*ZPH + 256 + k];
                    float zo = zb[384 + k] + zb[ZPH + 384 + k] + zb[2*ZPH + 384 + k] + zb[3*ZPH + 384 + k];
                    zi = fmaf(yt, cx.sWx[k],       zi + cx.sbl[k]);
                    zf = fmaf(yt, cx.sWx[128 + k], zf + cx.sbl[128 + k]);
                    zg = fmaf(yt, cx.sWx[256 + k], zg + cx.sbl[256 + k]);
                    zo = fmaf(yt, cx.sWx[384 + k], zo + cx.sbl[384 + k]);
                    float cold = cx.sc[k*8 + b];
                    cn = fmaf(sig_ap(zf), cold, sig_ap(zi) * tanh_ap(zg));
                    dn = sig_ap(zo) * tanh_ap(cn);
                }
                cx.sc[k*8 + b] = cn;
                cx.sd[k*8 + b] = dn;
            }
            __threadfence_block();
            if (t < T1 - 1) BARA(2, 1024);
            BARS(5, 512);
        }
    }
    __syncthreads();

    // ---- Epilogue ----
    if (wid < nb) {
        int b = wid;
        const float4* Xb = (const float4*)(X + (size_t)(b0 + b) * T1 * HE);
        float cxx = 0.f, cy = 0.f, cz = 0.f, cw = 0.f;
        for (int tp = 0; tp < T1; tp++) {
            float bb = cx.sbeta[b*128 + tp];
            float4 xv = Xb[tp*32 + lane];
            cxx = fmaf(bb, xv.x, cxx); cy = fmaf(bb, xv.y, cy);
            cz  = fmaf(bb, xv.z, cz);  cw = fmaf(bb, xv.w, cw);
        }
        float4 wfc2 = ((const float4*)(Wf + 128))[lane];
        float4 wfd  = ((const float4*)Wf)[lane];
        int e0 = lane * 4;
        float d0 = cx.sd[(e0+0)*8 + b], d1 = cx.sd[(e0+1)*8 + b];
        float d2 = cx.sd[(e0+2)*8 + b], d3 = cx.sd[(e0+3)*8 + b];
        float r = cxx*wfc2.x + cy*wfc2.y + cz*wfc2.z + cw*wfc2.w;
        r = fmaf(d0, wfd.x, r); r = fmaf(d1, wfd.y, r);
        r = fmaf(d2, wfd.z, r); r = fmaf(d3, wfd.w, r);
        #pragma unroll
        for (int m = 16; m; m >>= 1) r += __shfl_xor_sync(0xffffffffu, r, m);
        if (lane == 0) out[b0 + b] = r + bf[0];
    }
}

extern "C" void kernel_launch(void* const* d_in, const int* in_sizes, int n_in,
                              void* d_out, int out_size)
{
    const float* X    = (const float*)d_in[0];
    const float* yprev= (const float*)d_in[1];
    const float* W1   = (const float*)d_in[2];
    const float* b1   = (const float*)d_in[3];
    const float* W2   = (const float*)d_in[4];
    const float* b2   = (const float*)d_in[5];
    const float* Wfc  = (const float*)d_in[6];
    const float* bfc  = (const float*)d_in[7];
    const float* Wx   = (const float*)d_in[8];
    const float* Wh   = (const float*)d_in[9];
    const float* bl   = (const float*)d_in[10];
    const float* Wf   = (const float*)d_in[11];
    const float* bf   = (const float*)d_in[12];
    float* out = (float*)d_out;

    cudaFuncSetAttribute(prex_kernel, cudaFuncAttributeMaxDynamicSharedMemorySize, PRE_SMEM);
    cudaFuncSetAttribute(decoder_kernel, cudaFuncAttributeMaxDynamicSharedMemorySize, MAIN_SMEM);

    prex_kernel<<<BSZ, 256, PRE_SMEM>>>(X, W1, b1, Wfc, Wh);
    decoder_kernel<<<NCTA, THREADS, MAIN_SMEM>>>(X, yprev, W1, W2, b2, Wfc, bfc,
                                                 Wx, Wh, bl, Wf, bf, out);
}

// round 11
// speedup vs baseline: 1.0337x; 1.0337x over previous
#include <cuda_runtime.h>
#include <cuda_fp16.h>

#define BSZ 1024
#define T1  127
#define TP  128
#define HD  128
#define HE  128
#define ZD  512
#define GMAX 7
#define NCTA 147
#define THREADS 1024

__device__ __half g_prex[(size_t)BSZ * TP * HE];   // 33.5 MB, L2-resident
__device__ float  g_px2[BSZ * T1];

static __device__ __forceinline__ float tanh_ap(float x){
    float r; asm("tanh.approx.f32 %0, %1;" : "=f"(r) : "f"(x)); return r;
}
static __device__ __forceinline__ float sig_ap(float x){
    return fmaf(0.5f, tanh_ap(0.5f * x), 0.5f);
}
static __device__ __forceinline__ unsigned tanh2_ap(unsigned x){
    unsigned r; asm("tanh.approx.f16x2 %0, %1;" : "=r"(r) : "r"(x)); return r;
}
static __device__ __forceinline__ unsigned h2u(__half2 h){
    union { __half2 h; unsigned u; } v; v.h = h; return v.u;
}
static __device__ __forceinline__ __half2 u2h(unsigned u){
    union { __half2 h; unsigned u; } v; v.u = u; return v.h;
}

#define FMA2(d,a,b,c)  asm("fma.rn.f32x2 %0, %1, %2, %3;" : "=l"(d) : "l"(a), "l"(b), "l"(c))
#define PACKB(d,x)     asm("mov.b64 %0, {%1,%1};" : "=l"(d) : "f"(x))
#define UNPACK2(x,y,d) asm("mov.b64 {%0,%1}, %2;" : "=f"(x), "=f"(y) : "l"(d))

// ---------------------------------------------------------------------------
// Prepass: pre_x (fp16, padded) + px2
// ---------------------------------------------------------------------------
#define PRE_SMEM ((HD*HE + T1*HE) * 4)

__global__ void __launch_bounds__(256, 1)
prex_kernel(const float* __restrict__ X, const float* __restrict__ W1,
            const float* __restrict__ b1, const float* __restrict__ Wfc)
{
    extern __shared__ float sm[];
    float* sW = sm;
    float* sX = sm + HD * HE;
    int b = blockIdx.x;
    int tid = threadIdx.x, lane = tid & 31, wid = tid >> 5;
    const float* Xb = X + (size_t)b * T1 * HE;

    for (int i = tid; i < HD * HE; i += 256) sW[i] = W1[2 * HD * HE + i];
    for (int i = tid; i < T1 * HE; i += 256) sX[i] = Xb[i];
    __syncthreads();

    int e = tid & 127, th = tid >> 7;
    float b1e = b1[e];
    for (int t = th; t < T1; t += 2) {
        float acc = 0.f;
        const float* xr = sX + t * HE;
        #pragma unroll 8
        for (int k = 0; k < HE; k++) acc = fmaf(xr[k], sW[k * HE + e], acc);
        g_prex[((size_t)b * TP + t) * HE + e] = __float2half(acc + b1e);
    }
    if (tid < 128) g_prex[((size_t)b * TP + 127) * HE + tid] = __float2half(0.f);

    float4 wf = ((const float4*)Wfc)[lane];
    for (int t = wid; t < T1; t += 8) {
        float4 x = ((const float4*)(sX + t * HE))[lane];
        float p = x.x * wf.x + x.y * wf.y + x.z * wf.z + x.w * wf.w;
        #pragma unroll
        for (int m = 16; m; m >>= 1) p += __shfl_xor_sync(0xffffffffu, p, m);
        if (lane == 0) g_px2[b * T1 + t] = p;
    }
}

// ---------------------------------------------------------------------------
// Main kernel: 147 CTAs x 7 batches x 1024 threads (R8 structure)
// ---------------------------------------------------------------------------
#define O_W1H  0                        // half2[128*128] = 16384 floats
#define O_VA   16384                    // [8][7][128] = 7168
#define O_ZP   (O_VA + 7168)            // [4][7][512] = 14336
#define O_D    (O_ZP + 14336)           // 896
#define O_DD   (O_D + 896)              // dup f32x2 state: 896 ull = 1792 floats
#define O_C    (O_DD + 1792)            // 896
#define O_BETA (O_C + 896)              // 896
#define O_PX2  (O_BETA + 896)           // 896
#define O_PX2H (O_PX2 + 896)            // 896 (half2-dup px2)
#define O_YP   (O_PX2H + 896)           // 896
#define O_W2   (O_YP + 896)             // 128
#define O_WX   (O_W2 + 128)             // 512
#define O_BL   (O_WX + 512)             // 512
#define O_SSB  (O_BL + 512)             // 16
#define O_SQ   (O_SSB + 16)             // 8
#define MAIN_FLOATS (O_SQ + 8)
#define MAIN_SMEM (MAIN_FLOATS * 4)     // 184,928 B

struct Ctx {
    __half2* sW1h; float* sva; float* szp; float* sd; float* sdd; float* sc;
    float* sbeta; float* spx2; unsigned* spx2h; float* syp;
    float* sW2; float* sWx; float* sbl; float* ssb; float* sq;
};

// Phase B: one warp per (b, half); f16x2 attention, fp16 window dot with px2
static __device__ __forceinline__ void phaseB(const Ctx& cx, int b0, int b, int half_,
                                              int lane, bool last, float b2v)
{
    float4 vr = make_float4(0.f, 0.f, 0.f, 0.f);
    #pragma unroll
    for (int h = 0; h < 8; h++) {
        float4 a = ((const float4*)(cx.sva + h*896 + b*128))[lane];
        vr.x += a.x; vr.y += a.y; vr.z += a.z; vr.w += a.w;
    }
    float4 w2r = ((const float4*)cx.sW2)[lane];
    __half2 vr01 = __floats2half2_rn(vr.x, vr.y);
    __half2 vr23 = __floats2half2_rn(vr.z, vr.w);
    __half2 w01  = __floats2half2_rn(w2r.x, w2r.y);
    __half2 w23  = __floats2half2_rn(w2r.z, w2r.w);

    const uint2* pxb = ((const uint2*)(g_prex + (size_t)(b0 + b) * TP * HE)) + lane;
    const unsigned* px2h = cx.spx2h + b * 128;
    float s_l = 0.f;
    int tp0 = half_ * 64;

    uint2 c0 = pxb[(tp0+0)*32], c1 = pxb[(tp0+1)*32];
    uint2 c2 = pxb[(tp0+2)*32], c3 = pxb[(tp0+3)*32];

    #pragma unroll 1
    for (int tc = 0; tc < 64; tc += 4) {
        int tp = tp0 + tc;
        int tn = (tc + 4 < 64) ? tp + 4 : tp;
        uint2 n0 = pxb[(tn+0)*32], n1 = pxb[(tn+1)*32];
        uint2 n2 = pxb[(tn+2)*32], n3 = pxb[(tn+3)*32];

        __half2 h0a = u2h(tanh2_ap(h2u(__hadd2(u2h(c0.x), vr01))));
        __half2 h0b = u2h(tanh2_ap(h2u(__hadd2(u2h(c0.y), vr23))));
        __half2 h1a = u2h(tanh2_ap(h2u(__hadd2(u2h(c1.x), vr01))));
        __half2 h1b = u2h(tanh2_ap(h2u(__hadd2(u2h(c1.y), vr23))));
        __half2 h2a = u2h(tanh2_ap(h2u(__hadd2(u2h(c2.x), vr01))));
        __half2 h2b = u2h(tanh2_ap(h2u(__hadd2(u2h(c2.y), vr23))));
        __half2 h3a = u2h(tanh2_ap(h2u(__hadd2(u2h(c3.x), vr01))));
        __half2 h3b = u2h(tanh2_ap(h2u(__hadd2(u2h(c3.y), vr23))));

        __half2 p0 = __hfma2(h0b, w23, __hmul2(h0a, w01));
        __half2 p1 = __hfma2(h1b, w23, __hmul2(h1a, w01));
        __half2 p2 = __hfma2(h2b, w23, __hmul2(h2a, w01));
        __half2 p3 = __hfma2(h3b, w23, __hmul2(h3a, w01));

        // fp16 window dot with px2 (4 tp), folded to f32 once per window
        __half2 S2 = __hmul2(p3, u2h(px2h[tp+3]));
        S2 = __hfma2(p2, u2h(px2h[tp+2]), S2);
        S2 = __hfma2(p1, u2h(px2h[tp+1]), S2);
        S2 = __hfma2(p0, u2h(px2h[tp+0]), S2);
        float2 sw = __half22float2(S2);
        s_l += sw.x + sw.y;

        if (last) {
            float2 q0 = __half22float2(p0);
            float2 q1 = __half22float2(p1);
            float2 q2 = __half22float2(p2);
            float2 q3 = __half22float2(p3);
            float r0 = q0.x + q0.y, r1 = q1.x + q1.y;
            float r2 = q2.x + q2.y, r3 = q3.x + q3.y;
            #pragma unroll
            for (int m = 16; m; m >>= 1) {
                r0 += __shfl_xor_sync(0xffffffffu, r0, m);
                r1 += __shfl_xor_sync(0xffffffffu, r1, m);
                r2 += __shfl_xor_sync(0xffffffffu, r2, m);
                r3 += __shfl_xor_sync(0xffffffffu, r3, m);
            }
            if (lane == 0) {
                cx.sbeta[b*128 + tp+0] = r0 + b2v;
                cx.sbeta[b*128 + tp+1] = r1 + b2v;
                cx.sbeta[b*128 + tp+2] = r2 + b2v;
                cx.sbeta[b*128 + tp+3] = r3 + b2v;
            }
        }
        c0 = n0; c1 = n1; c2 = n2; c3 = n3;
    }
    #pragma unroll
    for (int m = 16; m; m >>= 1) s_l += __shfl_xor_sync(0xffffffffu, s_l, m);
    if (lane == 0) cx.ssb[2*b + half_] = s_l;
}

// Phase C: zp = d @ Wh (fp32 Wh direct from gmem; dup'd d pairs from smem)
static __device__ __forceinline__ void phaseC(const Ctx& cx, const float* __restrict__ Wh,
                                              int ctid)
{
    int jg = ctid & 127, h = ctid >> 7, kb = h * 32;
    const float* whp = Wh + (size_t)kb * ZD + jg * 4;
    unsigned long long a01[GMAX], a23[GMAX];
    #pragma unroll
    for (int b = 0; b < GMAX; b++) { a01[b] = 0ULL; a23[b] = 0ULL; }

    // w rows prefetched 4 ahead; each ulonglong2 = ((j0,j1),(j2,j3)) packed f32x2
    ulonglong2 w0 = *(const ulonglong2*)(whp + 0*ZD);
    ulonglong2 w1 = *(const ulonglong2*)(whp + 1*ZD);
    ulonglong2 w2 = *(const ulonglong2*)(whp + 2*ZD);
    ulonglong2 w3 = *(const ulonglong2*)(whp + 3*ZD);

#define CPAIR(WA, WB, K) do { \
    _Pragma("unroll") \
    for (int b = 0; b < GMAX; b++) { \
        ulonglong2 dd = *(const ulonglong2*)(cx.sdd + (b*128 + (K))*2); \
        FMA2(a01[b], dd.x, (WA).x, a01[b]); FMA2(a23[b], dd.x, (WA).y, a23[b]); \
        FMA2(a01[b], dd.y, (WB).x, a01[b]); FMA2(a23[b], dd.y, (WB).y, a23[b]); \
    } \
} while(0)

    #pragma unroll 1
    for (int kk = 0; kk < 32; kk += 4) {
        int kn = (kk + 4 < 32) ? kk + 4 : kk;
        ulonglong2 n0 = *(const ulonglong2*)(whp + (size_t)(kn+0)*ZD);
        ulonglong2 n1 = *(const ulonglong2*)(whp + (size_t)(kn+1)*ZD);
        ulonglong2 n2 = *(const ulonglong2*)(whp + (size_t)(kn+2)*ZD);
        ulonglong2 n3 = *(const ulonglong2*)(whp + (size_t)(kn+3)*ZD);
        CPAIR(w0, w1, kb + kk);
        CPAIR(w2, w3, kb + kk + 2);
        w0 = n0; w1 = n1; w2 = n2; w3 = n3;
    }
#undef CPAIR
    #pragma unroll
    for (int b = 0; b < GMAX; b++) {
        float4 r;
        UNPACK2(r.x, r.y, a01[b]);
        UNPACK2(r.z, r.w, a23[b]);
        *(float4*)(cx.szp + h*3584 + b*512 + jg*4) = r;
    }
}

__global__ void __launch_bounds__(THREADS, 1)
decoder_kernel(const float* __restrict__ X, const float* __restrict__ yprev,
               const float* __restrict__ W1, const float* __restrict__ W2,
               const float* __restrict__ b2, const float* __restrict__ Wfc,
               const float* __restrict__ bfc, const float* __restrict__ Wx,
               const float* __restrict__ Wh, const float* __restrict__ bl,
               const float* __restrict__ Wf, const float* __restrict__ bf,
               float* __restrict__ out)
{
    extern __shared__ float sm[];
    Ctx cx;
    cx.sW1h = (__half2*)(sm + O_W1H);
    cx.sva = sm + O_VA;  cx.szp = sm + O_ZP;
    cx.sd = sm + O_D;    cx.sdd = sm + O_DD;  cx.sc = sm + O_C;
    cx.sbeta = sm + O_BETA;
    cx.spx2 = sm + O_PX2; cx.spx2h = (unsigned*)(sm + O_PX2H);
    cx.syp = sm + O_YP;  cx.sW2 = sm + O_W2;
    cx.sWx = sm + O_WX;  cx.sbl = sm + O_BL;  cx.ssb = sm + O_SSB; cx.sq = sm + O_SQ;

    int tid = threadIdx.x, lane = tid & 31, wid = tid >> 5;
    int b0 = blockIdx.x * GMAX;
    if (b0 >= BSZ) return;
    int nb = min(GMAX, BSZ - b0);

    for (int i = tid; i < HD * HE; i += THREADS)
        cx.sW1h[i] = __floats2half2_rn(W1[i], W1[HD * HE + i]);
    if (tid < 128) cx.sW2[tid] = W2[tid];
    if (tid < 512) { cx.sWx[tid] = Wx[tid]; cx.sbl[tid] = bl[tid]; }
    if (tid < 16) cx.ssb[tid] = 0.f;
    if (tid >= 16 && tid < 24) cx.sq[tid - 16] = 0.f;
    if (tid < GMAX * 128) {
        int b = tid >> 7, tp = tid & 127;
        bool ok = (b < nb) && (tp < T1);
        float v = ok ? g_px2[(b0 + b) * T1 + tp] : 0.f;
        cx.spx2[tid] = v;
        cx.spx2h[tid] = h2u(__floats2half2_rn(v, v));
        cx.syp[tid]  = ok ? yprev[(size_t)(b0 + b) * T1 + tp] : 0.f;
        float x00 = (b < nb) ? X[(size_t)(b0 + b) * T1 * HE] : 0.f;
        cx.sd[tid] = x00; cx.sc[tid] = x00;
        unsigned long long dp; PACKB(dp, x00);
        *(unsigned long long*)(cx.sdd + tid*2) = dp;
    }
    float b2v  = b2[0];
    float bfcv = bfc[0];
    float wfcy = Wfc[HE];
    __syncthreads();
    if (wid < nb) {
        const float* p = cx.spx2 + wid * 128;
        float v = p[lane] + p[lane+32] + p[lane+64] + p[lane+96];
        #pragma unroll
        for (int m = 16; m; m >>= 1) v += __shfl_xor_sync(0xffffffffu, v, m);
        if (lane == 0) cx.sq[wid] = v;
    }
    __syncthreads();

    for (int t = 0; t < T1; t++) {
        // ---- Phase A: v partials (fp16 W1, 8-way k-split, all 32 warps) ----
        {
            int e = tid & 127, h = tid >> 7, kb = h * 16;
            float acc[GMAX];
            #pragma unroll
            for (int b = 0; b < GMAX; b++) acc[b] = 0.f;
            #pragma unroll
            for (int kk = 0; kk < 16; kk += 4) {
                int k = kb + kk;
                float2 w0 = __half22float2(cx.sW1h[(k+0)*128 + e]);
                float2 w1 = __half22float2(cx.sW1h[(k+1)*128 + e]);
                float2 w2 = __half22float2(cx.sW1h[(k+2)*128 + e]);
                float2 w3 = __half22float2(cx.sW1h[(k+3)*128 + e]);
                #pragma unroll
                for (int b = 0; b < GMAX; b++) {
                    float4 dv = *(const float4*)(cx.sd + b*128 + k);
                    float4 cv = *(const float4*)(cx.sc + b*128 + k);
                    float a = acc[b];
                    a = fmaf(dv.x, w0.x, a); a = fmaf(cv.x, w0.y, a);
                    a = fmaf(dv.y, w1.x, a); a = fmaf(cv.y, w1.y, a);
                    a = fmaf(dv.z, w2.x, a); a = fmaf(cv.z, w2.y, a);
                    a = fmaf(dv.w, w3.x, a); a = fmaf(cv.w, w3.y, a);
                    acc[b] = a;
                }
            }
            #pragma unroll
            for (int b = 0; b < GMAX; b++) cx.sva[h*896 + b*128 + e] = acc[b];
        }
        __syncthreads();

        // ---- BC region: warps 0-13 attention, warps 16-31 d@Wh ----
        {
            bool last = (t == T1 - 1);
            if (wid < 14) {
                int b = wid >> 1;
                if (b < nb) phaseB(cx, b0, b, wid & 1, lane, last, b2v);
            } else if (wid >= 16) {
                phaseC(cx, Wh, tid - 512);
            }
        }
        __syncthreads();

        // ---- Phase D: assemble z, gates, update d/c + dup state ----
        if (tid < GMAX * 128) {
            int b = tid >> 7, k = tid & 127;
            float s  = cx.ssb[2*b] + cx.ssb[2*b+1] + b2v * cx.sq[b];
            float yt = fmaf(cx.syp[b*128 + t], wfcy, s + bfcv);
            const float* zp = cx.szp + b * 512;
            float zi = zp[k]     + zp[3584 + k]     + zp[7168 + k]     + zp[10752 + k];
            float zf = zp[128+k] + zp[3584 + 128+k] + zp[7168 + 128+k] + zp[10752 + 128+k];
            float zg = zp[256+k] + zp[3584 + 256+k] + zp[7168 + 256+k] + zp[10752 + 256+k];
            float zo = zp[384+k] + zp[3584 + 384+k] + zp[7168 + 384+k] + zp[10752 + 384+k];
            zi = fmaf(yt, cx.sWx[k],     zi + cx.sbl[k]);
            zf = fmaf(yt, cx.sWx[128+k], zf + cx.sbl[128+k]);
            zg = fmaf(yt, cx.sWx[256+k], zg + cx.sbl[256+k]);
            zo = fmaf(yt, cx.sWx[384+k], zo + cx.sbl[384+k]);
            float cn = fmaf(sig_ap(zf), cx.sc[tid], sig_ap(zi) * tanh_ap(zg));
            float dn = sig_ap(zo) * tanh_ap(cn);
            cx.sc[tid] = cn;
            cx.sd[tid] = dn;
            unsigned long long dp; PACKB(dp, dn);
            *(unsigned long long*)(cx.sdd + tid*2) = dp;
        }
        __syncthreads();
    }

    // ---- Epilogue ----
    if (wid < nb) {
        int b = wid;
        const float4* Xb = (const float4*)(X + (size_t)(b0 + b) * T1 * HE);
        float cxx = 0.f, cy = 0.f, cz = 0.f, cw = 0.f;
        for (int tp = 0; tp < T1; tp++) {
            float bb = cx.sbeta[b*128 + tp];
            float4 xv = Xb[tp*32 + lane];
            cxx = fmaf(bb, xv.x, cxx); cy = fmaf(bb, xv.y, cy);
            cz  = fmaf(bb, xv.z, cz);  cw = fmaf(bb, xv.w, cw);
        }
        float4 wfc2 = ((const float4*)(Wf + 128))[lane];
        float4 wfd  = ((const float4*)Wf)[lane];
        float4 dv   = ((const float4*)(cx.sd + b*128))[lane];
        float r = cxx*wfc2.x + cy*wfc2.y + cz*wfc2.z + cw*wfc2.w;
        r = fmaf(dv.x, wfd.x, r); r = fmaf(dv.y, wfd.y, r);
        r = fmaf(dv.z, wfd.z, r); r = fmaf(dv.w, wfd.w, r);
        #pragma unroll
        for (int m = 16; m; m >>= 1) r += __shfl_xor_sync(0xffffffffu, r, m);
        if (lane == 0) out[b0 + b] = r + bf[0];
    }
}

extern "C" void kernel_launch(void* const* d_in, const int* in_sizes, int n_in,
                              void* d_out, int out_size)
{
    const float* X    = (const float*)d_in[0];
    const float* yprev= (const float*)d_in[1];
    const float* W1   = (const float*)d_in[2];
    const float* b1   = (const float*)d_in[3];
    const float* W2   = (const float*)d_in[4];
    const float* b2   = (const float*)d_in[5];
    const float* Wfc  = (const float*)d_in[6];
    const float* bfc  = (const float*)d_in[7];
    const float* Wx   = (const float*)d_in[8];
    const float* Wh   = (const float*)d_in[9];
    const float* bl   = (const float*)d_in[10];
    const float* Wf   = (const float*)d_in[11];
    const float* bf   = (const float*)d_in[12];
    float* out = (float*)d_out;

    cudaFuncSetAttribute(prex_kernel, cudaFuncAttributeMaxDynamicSharedMemorySize, PRE_SMEM);
    cudaFuncSetAttribute(decoder_kernel, cudaFuncAttributeMaxDynamicSharedMemorySize, MAIN_SMEM);

    prex_kernel<<<BSZ, 256, PRE_SMEM>>>(X, W1, b1, Wfc);
    decoder_kernel<<<NCTA, THREADS, MAIN_SMEM>>>(X, yprev, W1, W2, b2, Wfc, bfc,
                                                 Wx, Wh, bl, Wf, bf, out);
}

// round 12
// speedup vs baseline: 1.3657x; 1.3211x over previous
#include <cuda_runtime.h>
#include <cuda_fp16.h>

#define BSZ 1024
#define T1  127
#define TP  128
#define HD  128
#define HE  128
#define ZD  512
#define GMAX 7
#define NCTA 147
#define THREADS 1024
#define SVAS 132      // sva row stride (floats)
#define ZPS  516      // szp row stride (floats)
#define DCS  264      // sdch row stride (halves)

__device__ __half g_prex[(size_t)BSZ * TP * HE];   // 33.5 MB, L2-resident
__device__ float  g_px2[BSZ * T1];
__device__ uint2  g_whf[8 * 64 * 32];              // Wh fragment-packed fp16
__device__ uint2  g_w1f[16 * 16 * 32];             // W1(d|c) fragment-packed fp16

static __device__ __forceinline__ float tanh_ap(float x){
    float r; asm("tanh.approx.f32 %0, %1;" : "=f"(r) : "f"(x)); return r;
}
static __device__ __forceinline__ float sig_ap(float x){
    return fmaf(0.5f, tanh_ap(0.5f * x), 0.5f);
}
static __device__ __forceinline__ unsigned tanh2_ap(unsigned x){
    unsigned r; asm("tanh.approx.f16x2 %0, %1;" : "=r"(r) : "r"(x)); return r;
}
static __device__ __forceinline__ unsigned h2u(__half2 h){
    union { __half2 h; unsigned u; } v; v.h = h; return v.u;
}
static __device__ __forceinline__ __half2 u2h(unsigned u){
    union { __half2 h; unsigned u; } v; v.u = u; return v.h;
}

#define MMA16816(d0,d1,d2,d3,a0,a1,a2,a3,b0,b1) \
    asm volatile("mma.sync.aligned.m16n8k16.row.col.f32.f16.f16.f32 " \
        "{%0,%1,%2,%3}, {%4,%5,%6,%7}, {%8,%9}, {%0,%1,%2,%3};" \
        : "+f"(d0),"+f"(d1),"+f"(d2),"+f"(d3) \
        : "r"(a0),"r"(a1),"r"(a2),"r"(a3),"r"(b0),"r"(b1))

#define LDSM4(a0,a1,a2,a3,addr) \
    asm volatile("ldmatrix.sync.aligned.m8n8.x4.shared.b16 {%0,%1,%2,%3}, [%4];" \
        : "=r"(a0),"=r"(a1),"=r"(a2),"=r"(a3) : "r"(addr))

// ---------------------------------------------------------------------------
// Prepass: pre_x fp16 + px2 + fragment-packing of Wh and W1
// ---------------------------------------------------------------------------
#define PRE_SMEM ((HD*HE + T1*HE) * 4)

__global__ void __launch_bounds__(256, 1)
prex_kernel(const float* __restrict__ X, const float* __restrict__ W1,
            const float* __restrict__ b1, const float* __restrict__ Wfc,
            const float* __restrict__ Wh)
{
    extern __shared__ float sm[];
    float* sW = sm;
    float* sX = sm + HD * HE;
    int b = blockIdx.x;
    int tid = threadIdx.x, lane = tid & 31, wid = tid >> 5;
    const float* Xb = X + (size_t)b * T1 * HE;

    // fragment packing (m16n8k16 B-frag, col layout: k=(L%4)*2{,+1,+8,+9}, n=L/4)
    if (b < 64) {           // g_whf: 16384 uint2
        int idx = b * 256 + tid;
        int kt = idx >> 11, nt = (idx >> 5) & 63, L = idx & 31;
        int kb = kt * 16 + (L & 3) * 2, n = nt * 8 + (L >> 2);
        g_whf[idx] = make_uint2(
            h2u(__floats2half2_rn(Wh[(size_t)kb*ZD + n],     Wh[(size_t)(kb+1)*ZD + n])),
            h2u(__floats2half2_rn(Wh[(size_t)(kb+8)*ZD + n], Wh[(size_t)(kb+9)*ZD + n])));
    } else if (b < 96) {    // g_w1f: 8192 uint2 (W1 rows 0..255 = W1_d|W1_c)
        int idx = (b - 64) * 256 + tid;
        int kt = idx >> 9, nt = (idx >> 5) & 15, L = idx & 31;
        int kb = kt * 16 + (L & 3) * 2, n = nt * 8 + (L >> 2);
        g_w1f[idx] = make_uint2(
            h2u(__floats2half2_rn(W1[kb*HE + n],     W1[(kb+1)*HE + n])),
            h2u(__floats2half2_rn(W1[(kb+8)*HE + n], W1[(kb+9)*HE + n])));
    }

    for (int i = tid; i < HD * HE; i += 256) sW[i] = W1[2 * HD * HE + i];
    for (int i = tid; i < T1 * HE; i += 256) sX[i] = Xb[i];
    __syncthreads();

    int e = tid & 127, th = tid >> 7;
    float b1e = b1[e];
    for (int t = th; t < T1; t += 2) {
        float acc = 0.f;
        const float* xr = sX + t * HE;
        #pragma unroll 8
        for (int k = 0; k < HE; k++) acc = fmaf(xr[k], sW[k * HE + e], acc);
        g_prex[((size_t)b * TP + t) * HE + e] = __float2half(acc + b1e);
    }
    if (tid < 128) g_prex[((size_t)b * TP + 127) * HE + tid] = __float2half(0.f);

    float4 wf = ((const float4*)Wfc)[lane];
    for (int t = wid; t < T1; t += 8) {
        float4 x = ((const float4*)(sX + t * HE))[lane];
        float p = x.x * wf.x + x.y * wf.y + x.z * wf.z + x.w * wf.w;
        #pragma unroll
        for (int m = 16; m; m >>= 1) p += __shfl_xor_sync(0xffffffffu, p, m);
        if (lane == 0) g_px2[b * T1 + t] = p;
    }
}

// ---------------------------------------------------------------------------
// Main kernel: 147 CTAs x 7 batches x 1024 threads; A/C on tensor cores
// ---------------------------------------------------------------------------
#define O_VA   0                        // [7][132] = 924
#define O_ZP   924                      // [7][516] = 3612
#define O_DCH  (O_ZP + 3612)            // [16][264] half = 2112 floats
#define O_D    (O_DCH + 2112)           // 896
#define O_C    (O_D + 896)              // 896
#define O_BETA (O_C + 896)              // 896
#define O_PX2  (O_BETA + 896)           // 896
#define O_YP   (O_PX2 + 896)            // 896
#define O_W2   (O_YP + 896)             // 128
#define O_WX   (O_W2 + 128)             // 512
#define O_BL   (O_WX + 512)             // 512
#define O_SSB  (O_BL + 512)             // 16
#define O_SQ   (O_SSB + 16)             // 8
#define MAIN_FLOATS (O_SQ + 8)
#define MAIN_SMEM (MAIN_FLOATS * 4)     // ~49.7 KB

struct Ctx {
    float* sva; float* szp; __half* sdch; float* sd; float* sc; float* sbeta;
    float* spx2; float* syp; float* sW2; float* sWx; float* sbl; float* ssb; float* sq;
};

// Phase B: one warp per (b, half); R8 numerics; vr from single-accum sva
static __device__ __forceinline__ void phaseB(const Ctx& cx, int b0, int b, int half_,
                                              int lane, bool last, float b2v)
{
    float4 vr = *(const float4*)(cx.sva + b * SVAS + lane * 4);
    float4 w2r = ((const float4*)cx.sW2)[lane];
    __half2 vr01 = __floats2half2_rn(vr.x, vr.y);
    __half2 vr23 = __floats2half2_rn(vr.z, vr.w);
    __half2 w01  = __floats2half2_rn(w2r.x, w2r.y);
    __half2 w23  = __floats2half2_rn(w2r.z, w2r.w);

    const uint2* pxb = ((const uint2*)(g_prex + (size_t)(b0 + b) * TP * HE)) + lane;
    const float* px2b = cx.spx2 + b * 128;
    float s_l = 0.f;
    int tp0 = half_ * 64;

    uint2 c0 = pxb[(tp0+0)*32], c1 = pxb[(tp0+1)*32];
    uint2 c2 = pxb[(tp0+2)*32], c3 = pxb[(tp0+3)*32];

    #pragma unroll 1
    for (int tc = 0; tc < 64; tc += 4) {
        int tp = tp0 + tc;
        int tn = (tc + 4 < 64) ? tp + 4 : tp;
        uint2 n0 = pxb[(tn+0)*32], n1 = pxb[(tn+1)*32];
        uint2 n2 = pxb[(tn+2)*32], n3 = pxb[(tn+3)*32];

        __half2 h0a = u2h(tanh2_ap(h2u(__hadd2(u2h(c0.x), vr01))));
        __half2 h0b = u2h(tanh2_ap(h2u(__hadd2(u2h(c0.y), vr23))));
        __half2 h1a = u2h(tanh2_ap(h2u(__hadd2(u2h(c1.x), vr01))));
        __half2 h1b = u2h(tanh2_ap(h2u(__hadd2(u2h(c1.y), vr23))));
        __half2 h2a = u2h(tanh2_ap(h2u(__hadd2(u2h(c2.x), vr01))));
        __half2 h2b = u2h(tanh2_ap(h2u(__hadd2(u2h(c2.y), vr23))));
        __half2 h3a = u2h(tanh2_ap(h2u(__hadd2(u2h(c3.x), vr01))));
        __half2 h3b = u2h(tanh2_ap(h2u(__hadd2(u2h(c3.y), vr23))));

        __half2 p0 = __hfma2(h0b, w23, __hmul2(h0a, w01));
        __half2 p1 = __hfma2(h1b, w23, __hmul2(h1a, w01));
        __half2 p2 = __hfma2(h2b, w23, __hmul2(h2a, w01));
        __half2 p3 = __hfma2(h3b, w23, __hmul2(h3a, w01));
        float2 q0 = __half22float2(p0);
        float2 q1 = __half22float2(p1);
        float2 q2 = __half22float2(p2);
        float2 q3 = __half22float2(p3);
        float pl0 = q0.x + q0.y, pl1 = q1.x + q1.y;
        float pl2 = q2.x + q2.y, pl3 = q3.x + q3.y;

        s_l = fmaf(pl0, px2b[tp+0], s_l);
        s_l = fmaf(pl1, px2b[tp+1], s_l);
        s_l = fmaf(pl2, px2b[tp+2], s_l);
        s_l = fmaf(pl3, px2b[tp+3], s_l);

        if (last) {
            float r0 = pl0, r1 = pl1, r2 = pl2, r3 = pl3;
            #pragma unroll
            for (int m = 16; m; m >>= 1) {
                r0 += __shfl_xor_sync(0xffffffffu, r0, m);
                r1 += __shfl_xor_sync(0xffffffffu, r1, m);
                r2 += __shfl_xor_sync(0xffffffffu, r2, m);
                r3 += __shfl_xor_sync(0xffffffffu, r3, m);
            }
            if (lane == 0) {
                cx.sbeta[b*128 + tp+0] = r0 + b2v;
                cx.sbeta[b*128 + tp+1] = r1 + b2v;
                cx.sbeta[b*128 + tp+2] = r2 + b2v;
                cx.sbeta[b*128 + tp+3] = r3 + b2v;
            }
        }
        c0 = n0; c1 = n1; c2 = n2; c3 = n3;
    }
    #pragma unroll
    for (int m = 16; m; m >>= 1) s_l += __shfl_xor_sync(0xffffffffu, s_l, m);
    if (lane == 0) cx.ssb[2*b + half_] = s_l;
}

__global__ void __launch_bounds__(THREADS, 1)
decoder_kernel(const float* __restrict__ X, const float* __restrict__ yprev,
               const float* __restrict__ W1, const float* __restrict__ W2,
               const float* __restrict__ b2, const float* __restrict__ Wfc,
               const float* __restrict__ bfc, const float* __restrict__ Wx,
               const float* __restrict__ Wh, const float* __restrict__ bl,
               const float* __restrict__ Wf, const float* __restrict__ bf,
               float* __restrict__ out)
{
    extern __shared__ float sm[];
    Ctx cx;
    cx.sva = sm + O_VA;  cx.szp = sm + O_ZP;  cx.sdch = (__half*)(sm + O_DCH);
    cx.sd = sm + O_D;    cx.sc = sm + O_C;    cx.sbeta = sm + O_BETA;
    cx.spx2 = sm + O_PX2; cx.syp = sm + O_YP; cx.sW2 = sm + O_W2;
    cx.sWx = sm + O_WX;  cx.sbl = sm + O_BL;  cx.ssb = sm + O_SSB; cx.sq = sm + O_SQ;

    int tid = threadIdx.x, lane = tid & 31, wid = tid >> 5;
    int b0 = blockIdx.x * GMAX;
    if (b0 >= BSZ) return;
    int nb = min(GMAX, BSZ - b0);

    if (tid < 128) cx.sW2[tid] = W2[tid];
    if (tid < 512) { cx.sWx[tid] = Wx[tid]; cx.sbl[tid] = bl[tid]; }
    if (tid < 16) cx.ssb[tid] = 0.f;
    if (tid >= 16 && tid < 24) cx.sq[tid - 16] = 0.f;
    for (int i = tid; i < 16 * DCS; i += THREADS) cx.sdch[i] = __float2half(0.f);
    __syncthreads();
    if (tid < GMAX * 128) {
        int b = tid >> 7, k = tid & 127;
        bool ok = (b < nb) && (k < T1);
        cx.spx2[tid] = ok ? g_px2[(b0 + b) * T1 + k] : 0.f;
        cx.syp[tid]  = ok ? yprev[(size_t)(b0 + b) * T1 + k] : 0.f;
        float x00 = (b < nb) ? X[(size_t)(b0 + b) * T1 * HE] : 0.f;
        cx.sd[tid] = x00; cx.sc[tid] = x00;
        __half xh = __float2half(x00);
        cx.sdch[b * DCS + k] = xh;
        cx.sdch[b * DCS + 128 + k] = xh;
    }
    float b2v  = b2[0];
    float bfcv = bfc[0];
    float wfcy = Wfc[HE];
    __syncthreads();
    if (wid < nb) {
        const float* p = cx.spx2 + wid * 128;
        float v = p[lane] + p[lane+32] + p[lane+64] + p[lane+96];
        #pragma unroll
        for (int m = 16; m; m >>= 1) v += __shfl_xor_sync(0xffffffffu, v, m);
        if (lane == 0) cx.sq[wid] = v;
    }
    __syncthreads();

    // shared-space base address for ldmatrix (per-thread row pattern)
    unsigned dch_saddr = (unsigned)__cvta_generic_to_shared(cx.sdch)
                       + (lane % 16) * (DCS * 2) + (lane >> 4) * 16;
    int w = wid - 16;
    int row = lane >> 2;

    for (int t = 0; t < T1; t++) {
        // ---- Region 1: A-mma by warps 16-31 (v = [d|c] @ W1dc) ----
        if (w >= 0) {
            uint2 bw[16];
            #pragma unroll
            for (int kt = 0; kt < 16; kt++) bw[kt] = g_w1f[(kt*16 + w)*32 + lane];
            float d0 = 0.f, d1 = 0.f, d2 = 0.f, d3 = 0.f;
            #pragma unroll
            for (int kt = 0; kt < 16; kt++) {
                unsigned a0, a1, a2, a3;
                LDSM4(a0, a1, a2, a3, dch_saddr + kt * 32);
                MMA16816(d0, d1, d2, d3, a0, a1, a2, a3, bw[kt].x, bw[kt].y);
            }
            if (row < GMAX)
                *(float2*)(cx.sva + row * SVAS + w * 8 + (lane & 3) * 2) = make_float2(d0, d1);
        }
        __syncthreads();

        // ---- Region 2: B (warps 0-13) || C-mma (warps 16-31) ----
        {
            bool last = (t == T1 - 1);
            if (wid < 14) {
                int b = wid >> 1;
                if (b < nb) phaseB(cx, b0, b, wid & 1, lane, last, b2v);
            } else if (w >= 0) {
                float acc[16];
                #pragma unroll
                for (int i = 0; i < 16; i++) acc[i] = 0.f;
                uint2 bf[4];
                #pragma unroll
                for (int nt = 0; nt < 4; nt++) bf[nt] = g_whf[(w*4 + nt)*32 + lane];
                #pragma unroll
                for (int kt = 0; kt < 8; kt++) {
                    uint2 bn[4];
                    #pragma unroll
                    for (int nt = 0; nt < 4; nt++)
                        bn[nt] = (kt < 7) ? g_whf[((kt+1)*64 + w*4 + nt)*32 + lane] : bf[nt];
                    unsigned a0, a1, a2, a3;
                    LDSM4(a0, a1, a2, a3, dch_saddr + kt * 32);
                    MMA16816(acc[0],  acc[1],  acc[2],  acc[3],  a0,a1,a2,a3, bf[0].x, bf[0].y);
                    MMA16816(acc[4],  acc[5],  acc[6],  acc[7],  a0,a1,a2,a3, bf[1].x, bf[1].y);
                    MMA16816(acc[8],  acc[9],  acc[10], acc[11], a0,a1,a2,a3, bf[2].x, bf[2].y);
                    MMA16816(acc[12], acc[13], acc[14], acc[15], a0,a1,a2,a3, bf[3].x, bf[3].y);
                    #pragma unroll
                    for (int nt = 0; nt < 4; nt++) bf[nt] = bn[nt];
                }
                if (row < GMAX) {
                    float* zb = cx.szp + row * ZPS + w * 32 + (lane & 3) * 2;
                    #pragma unroll
                    for (int nt = 0; nt < 4; nt++)
                        *(float2*)(zb + nt * 8) = make_float2(acc[nt*4], acc[nt*4+1]);
                }
            }
        }
        __syncthreads();

        // ---- Region 3: D — gates, state update (all warps, 896 threads) ----
        if (tid < GMAX * 128) {
            int b = tid >> 7, k = tid & 127;
            float s  = cx.ssb[2*b] + cx.ssb[2*b+1] + b2v * cx.sq[b];
            float yt = fmaf(cx.syp[b*128 + t], wfcy, s + bfcv);
            const float* zb = cx.szp + b * ZPS;
            float zi = fmaf(yt, cx.sWx[k],     zb[k]     + cx.sbl[k]);
            float zf = fmaf(yt, cx.sWx[128+k], zb[128+k] + cx.sbl[128+k]);
            float zg = fmaf(yt, cx.sWx[256+k], zb[256+k] + cx.sbl[256+k]);
            float zo = fmaf(yt, cx.sWx[384+k], zb[384+k] + cx.sbl[384+k]);
            float cn = fmaf(sig_ap(zf), cx.sc[tid], sig_ap(zi) * tanh_ap(zg));
            float dn = sig_ap(zo) * tanh_ap(cn);
            cx.sc[tid] = cn;
            cx.sd[tid] = dn;
            cx.sdch[b * DCS + k]       = __float2half(dn);
            cx.sdch[b * DCS + 128 + k] = __float2half(cn);
        }
        __syncthreads();
    }

    // ---- Epilogue: ctx from final beta; out ----
    if (wid < nb) {
        int b = wid;
        const float4* Xb = (const float4*)(X + (size_t)(b0 + b) * T1 * HE);
        float cxx = 0.f, cy = 0.f, cz = 0.f, cw = 0.f;
        for (int tp = 0; tp < T1; tp++) {
            float bb = cx.sbeta[b*128 + tp];
            float4 xv = Xb[tp*32 + lane];
            cxx = fmaf(bb, xv.x, cxx); cy = fmaf(bb, xv.y, cy);
            cz  = fmaf(bb, xv.z, cz);  cw = fmaf(bb, xv.w, cw);
        }
        float4 wfc2 = ((const float4*)(Wf + 128))[lane];
        float4 wfd  = ((const float4*)Wf)[lane];
        float4 dv   = ((const float4*)(cx.sd + b*128))[lane];
        float r = cxx*wfc2.x + cy*wfc2.y + cz*wfc2.z + cw*wfc2.w;
        r = fmaf(dv.x, wfd.x, r); r = fmaf(dv.y, wfd.y, r);
        r = fmaf(dv.z, wfd.z, r); r = fmaf(dv.w, wfd.w, r);
        #pragma unroll
        for (int m = 16; m; m >>= 1) r += __shfl_xor_sync(0xffffffffu, r, m);
        if (lane == 0) out[b0 + b] = r + bf[0];
    }
}

extern "C" void kernel_launch(void* const* d_in, const int* in_sizes, int n_in,
                              void* d_out, int out_size)
{
    const float* X    = (const float*)d_in[0];
    const float* yprev= (const float*)d_in[1];
    const float* W1   = (const float*)d_in[2];
    const float* b1   = (const float*)d_in[3];
    const float* W2   = (const float*)d_in[4];
    const float* b2   = (const float*)d_in[5];
    const float* Wfc  = (const float*)d_in[6];
    const float* bfc  = (const float*)d_in[7];
    const float* Wx   = (const float*)d_in[8];
    const float* Wh   = (const float*)d_in[9];
    const float* bl   = (const float*)d_in[10];
    const float* Wf   = (const float*)d_in[11];
    const float* bf   = (const float*)d_in[12];
    float* out = (float*)d_out;

    cudaFuncSetAttribute(prex_kernel, cudaFuncAttributeMaxDynamicSharedMemorySize, PRE_SMEM);
    cudaFuncSetAttribute(decoder_kernel, cudaFuncAttributeMaxDynamicSharedMemorySize, MAIN_SMEM);

    prex_kernel<<<BSZ, 256, PRE_SMEM>>>(X, W1, b1, Wfc, Wh);
    decoder_kernel<<<NCTA, THREADS, MAIN_SMEM>>>(X, yprev, W1, W2, b2, Wfc, bfc,
                                                 Wx, Wh, bl, Wf, bf, out);
}

// round 13
// speedup vs baseline: 1.9885x; 1.4561x over previous
#include <cuda_runtime.h>
#include <cuda_fp16.h>

#define BSZ 1024
#define T1  127
#define TP  128
#define HD  128
#define HE  128
#define ZD  512
#define GMAX 7
#define NCTA 147
#define THREADS 1024
#define SVAS 132
#define ZPS  516
#define DCS  264

__device__ __half g_prex[(size_t)BSZ * TP * HE];   // 33.5 MB, L2-resident
__device__ float  g_px2[BSZ * T1];
__device__ uint2  g_whf[8 * 64 * 32];              // Wh  fragment-packed fp16
__device__ uint2  g_w1f[16 * 16 * 32];             // W1(d|c) fragment-packed
__device__ uint2  g_w1xf[8 * 16 * 32];             // W1_x fragment-packed

static __device__ __forceinline__ float tanh_ap(float x){
    float r; asm("tanh.approx.f32 %0, %1;" : "=f"(r) : "f"(x)); return r;
}
static __device__ __forceinline__ float sig_ap(float x){
    return fmaf(0.5f, tanh_ap(0.5f * x), 0.5f);
}
static __device__ __forceinline__ unsigned tanh2_ap(unsigned x){
    unsigned r; asm("tanh.approx.f16x2 %0, %1;" : "=r"(r) : "r"(x)); return r;
}
static __device__ __forceinline__ unsigned h2u(__half2 h){
    union { __half2 h; unsigned u; } v; v.h = h; return v.u;
}
static __device__ __forceinline__ __half2 u2h(unsigned u){
    union { __half2 h; unsigned u; } v; v.u = u; return v.h;
}

#define MMA16816(d0,d1,d2,d3,a0,a1,a2,a3,b0,b1) \
    asm volatile("mma.sync.aligned.m16n8k16.row.col.f32.f16.f16.f32 " \
        "{%0,%1,%2,%3}, {%4,%5,%6,%7}, {%8,%9}, {%0,%1,%2,%3};" \
        : "+f"(d0),"+f"(d1),"+f"(d2),"+f"(d3) \
        : "r"(a0),"r"(a1),"r"(a2),"r"(a3),"r"(b0),"r"(b1))

#define LDSM4(a0,a1,a2,a3,addr) \
    asm volatile("ldmatrix.sync.aligned.m8n8.x4.shared.b16 {%0,%1,%2,%3}, [%4];" \
        : "=r"(a0),"=r"(a1),"=r"(a2),"=r"(a3) : "r"(addr))

// ---------------------------------------------------------------------------
// Pack kernel: fragment-pack Wh, W1dc, W1x (runs before prex/decoder)
// ---------------------------------------------------------------------------
__global__ void __launch_bounds__(256, 1)
pack_kernel(const float* __restrict__ W1, const float* __restrict__ Wh)
{
    int bb = blockIdx.x, tid = threadIdx.x;
    if (bb < 64) {
        int idx = bb * 256 + tid;
        int kt = idx >> 11, nt = (idx >> 5) & 63, L = idx & 31;
        int kb = kt * 16 + (L & 3) * 2, n = nt * 8 + (L >> 2);
        g_whf[idx] = make_uint2(
            h2u(__floats2half2_rn(Wh[(size_t)kb*ZD + n],     Wh[(size_t)(kb+1)*ZD + n])),
            h2u(__floats2half2_rn(Wh[(size_t)(kb+8)*ZD + n], Wh[(size_t)(kb+9)*ZD + n])));
    } else if (bb < 96) {
        int idx = (bb - 64) * 256 + tid;
        int kt = idx >> 9, nt = (idx >> 5) & 15, L = idx & 31;
        int kb = kt * 16 + (L & 3) * 2, n = nt * 8 + (L >> 2);
        g_w1f[idx] = make_uint2(
            h2u(__floats2half2_rn(W1[kb*HE + n],     W1[(kb+1)*HE + n])),
            h2u(__floats2half2_rn(W1[(kb+8)*HE + n], W1[(kb+9)*HE + n])));
    } else {
        int idx = (bb - 96) * 256 + tid;
        int kt = idx >> 9, nt = (idx >> 5) & 15, L = idx & 31;
        int kb = 2*HD + kt * 16 + (L & 3) * 2, n = nt * 8 + (L >> 2);
        g_w1xf[idx] = make_uint2(
            h2u(__floats2half2_rn(W1[kb*HE + n],     W1[(kb+1)*HE + n])),
            h2u(__floats2half2_rn(W1[(kb+8)*HE + n], W1[(kb+9)*HE + n])));
    }
}

// ---------------------------------------------------------------------------
// Prepass: pre_x = X@W1_x + b1 via tensor cores; px2 from gmem
// ---------------------------------------------------------------------------
__global__ void __launch_bounds__(256, 1)
prex_kernel(const float* __restrict__ X, const float* __restrict__ b1,
            const float* __restrict__ Wfc)
{
    __shared__ __half sXh[128 * 136];   // 34816 B, row stride 136 halves
    int b = blockIdx.x;
    int tid = threadIdx.x, lane = tid & 31, wid = tid >> 5;
    const float* Xb = X + (size_t)b * T1 * HE;

    for (int i = tid; i < T1 * HE; i += 256) {
        int row = i >> 7, col = i & 127;
        sXh[row * 136 + col] = __float2half(Xb[i]);
    }
    if (tid < 128) sXh[127 * 136 + tid] = __float2half(0.f);
    __syncthreads();

    // px2 (fp32, straight from gmem)
    float4 wf = ((const float4*)Wfc)[lane];
    for (int t = wid; t < T1; t += 8) {
        float4 x = ((const float4*)(Xb + t * HE))[lane];
        float p = x.x * wf.x + x.y * wf.y + x.z * wf.z + x.w * wf.w;
        #pragma unroll
        for (int m = 16; m; m >>= 1) p += __shfl_xor_sync(0xffffffffu, p, m);
        if (lane == 0) g_px2[b * T1 + t] = p;
    }

    // mma: warp wid owns t-rows [wid*16, wid*16+16)
    unsigned sa = (unsigned)__cvta_generic_to_shared(sXh)
                + (wid * 16 + (lane & 15)) * 272 + (lane >> 4) * 16;
    unsigned af[8][4];
    #pragma unroll
    for (int kt = 0; kt < 8; kt++)
        LDSM4(af[kt][0], af[kt][1], af[kt][2], af[kt][3], sa + kt * 32);

    int t0 = wid * 16 + (lane >> 2);
    #pragma unroll 1
    for (int nt = 0; nt < 16; nt++) {
        float d0 = 0.f, d1 = 0.f, d2 = 0.f, d3 = 0.f;
        #pragma unroll
        for (int kt = 0; kt < 8; kt++) {
            uint2 bw = g_w1xf[(kt*16 + nt)*32 + lane];
            MMA16816(d0, d1, d2, d3, af[kt][0], af[kt][1], af[kt][2], af[kt][3],
                     bw.x, bw.y);
        }
        int e0 = nt * 8 + (lane & 3) * 2;
        float2 bb = *(const float2*)(b1 + e0);
        *(__half2*)(g_prex + ((size_t)b * TP + t0) * HE + e0) =
            __floats2half2_rn(d0 + bb.x, d1 + bb.y);
        *(__half2*)(g_prex + ((size_t)b * TP + t0 + 8) * HE + e0) =
            __floats2half2_rn(d2 + bb.x, d3 + bb.y);
    }
}

// ---------------------------------------------------------------------------
// Main kernel: 147 CTAs x 7 batches x 1024 threads; A/C on tensor cores
// ---------------------------------------------------------------------------
#define O_VA   0                        // [7][132] = 924
#define O_ZP   924                      // [7][516] = 3612
#define O_DCH  (O_ZP + 3612)            // [16][264] half = 2112 floats
#define O_D    (O_DCH + 2112)           // 896
#define O_C    (O_D + 896)              // 896
#define O_BETA (O_C + 896)              // 896
#define O_PX2  (O_BETA + 896)           // 896
#define O_YP   (O_PX2 + 896)            // 896
#define O_W2   (O_YP + 896)             // 128
#define O_WX   (O_W2 + 128)             // 512
#define O_BL   (O_WX + 512)             // 512
#define O_SSB  (O_BL + 512)             // 16
#define O_SQ   (O_SSB + 16)             // 8
#define O_WHF  (O_SQ + 8)               // 16384 uint2 = 32768 floats
#define MAIN_FLOATS (O_WHF + 32768)
#define MAIN_SMEM (MAIN_FLOATS * 4)     // ~180.3 KB

struct Ctx {
    float* sva; float* szp; __half* sdch; float* sd; float* sc; float* sbeta;
    float* spx2; float* syp; float* sW2; float* sWx; float* sbl; float* ssb;
    float* sq; uint2* swhf;
};

static __device__ __forceinline__ void phaseB(const Ctx& cx, int b0, int b, int half_,
                                              int lane, bool last, float b2v)
{
    float4 vr = *(const float4*)(cx.sva + b * SVAS + lane * 4);
    float4 w2r = ((const float4*)cx.sW2)[lane];
    __half2 vr01 = __floats2half2_rn(vr.x, vr.y);
    __half2 vr23 = __floats2half2_rn(vr.z, vr.w);
    __half2 w01  = __floats2half2_rn(w2r.x, w2r.y);
    __half2 w23  = __floats2half2_rn(w2r.z, w2r.w);

    const uint2* pxb = ((const uint2*)(g_prex + (size_t)(b0 + b) * TP * HE)) + lane;
    const float* px2b = cx.spx2 + b * 128;
    float s_l = 0.f;
    int tp0 = half_ * 64;

    uint2 c0 = pxb[(tp0+0)*32], c1 = pxb[(tp0+1)*32];
    uint2 c2 = pxb[(tp0+2)*32], c3 = pxb[(tp0+3)*32];

    #pragma unroll 1
    for (int tc = 0; tc < 64; tc += 4) {
        int tp = tp0 + tc;
        int tn = (tc + 4 < 64) ? tp + 4 : tp;
        uint2 n0 = pxb[(tn+0)*32], n1 = pxb[(tn+1)*32];
        uint2 n2 = pxb[(tn+2)*32], n3 = pxb[(tn+3)*32];

        __half2 h0a = u2h(tanh2_ap(h2u(__hadd2(u2h(c0.x), vr01))));
        __half2 h0b = u2h(tanh2_ap(h2u(__hadd2(u2h(c0.y), vr23))));
        __half2 h1a = u2h(tanh2_ap(h2u(__hadd2(u2h(c1.x), vr01))));
        __half2 h1b = u2h(tanh2_ap(h2u(__hadd2(u2h(c1.y), vr23))));
        __half2 h2a = u2h(tanh2_ap(h2u(__hadd2(u2h(c2.x), vr01))));
        __half2 h2b = u2h(tanh2_ap(h2u(__hadd2(u2h(c2.y), vr23))));
        __half2 h3a = u2h(tanh2_ap(h2u(__hadd2(u2h(c3.x), vr01))));
        __half2 h3b = u2h(tanh2_ap(h2u(__hadd2(u2h(c3.y), vr23))));

        __half2 p0 = __hfma2(h0b, w23, __hmul2(h0a, w01));
        __half2 p1 = __hfma2(h1b, w23, __hmul2(h1a, w01));
        __half2 p2 = __hfma2(h2b, w23, __hmul2(h2a, w01));
        __half2 p3 = __hfma2(h3b, w23, __hmul2(h3a, w01));
        float2 q0 = __half22float2(p0);
        float2 q1 = __half22float2(p1);
        float2 q2 = __half22float2(p2);
        float2 q3 = __half22float2(p3);
        float pl0 = q0.x + q0.y, pl1 = q1.x + q1.y;
        float pl2 = q2.x + q2.y, pl3 = q3.x + q3.y;

        s_l = fmaf(pl0, px2b[tp+0], s_l);
        s_l = fmaf(pl1, px2b[tp+1], s_l);
        s_l = fmaf(pl2, px2b[tp+2], s_l);
        s_l = fmaf(pl3, px2b[tp+3], s_l);

        if (last) {
            float r0 = pl0, r1 = pl1, r2 = pl2, r3 = pl3;
            #pragma unroll
            for (int m = 16; m; m >>= 1) {
                r0 += __shfl_xor_sync(0xffffffffu, r0, m);
                r1 += __shfl_xor_sync(0xffffffffu, r1, m);
                r2 += __shfl_xor_sync(0xffffffffu, r2, m);
                r3 += __shfl_xor_sync(0xffffffffu, r3, m);
            }
            if (lane == 0) {
                cx.sbeta[b*128 + tp+0] = r0 + b2v;
                cx.sbeta[b*128 + tp+1] = r1 + b2v;
                cx.sbeta[b*128 + tp+2] = r2 + b2v;
                cx.sbeta[b*128 + tp+3] = r3 + b2v;
            }
        }
        c0 = n0; c1 = n1; c2 = n2; c3 = n3;
    }
    #pragma unroll
    for (int m = 16; m; m >>= 1) s_l += __shfl_xor_sync(0xffffffffu, s_l, m);
    if (lane == 0) cx.ssb[2*b + half_] = s_l;
}

__global__ void __launch_bounds__(THREADS, 1)
decoder_kernel(const float* __restrict__ X, const float* __restrict__ yprev,
               const float* __restrict__ W1, const float* __restrict__ W2,
               const float* __restrict__ b2, const float* __restrict__ Wfc,
               const float* __restrict__ bfc, const float* __restrict__ Wx,
               const float* __restrict__ Wh, const float* __restrict__ bl,
               const float* __restrict__ Wf, const float* __restrict__ bf,
               float* __restrict__ out)
{
    extern __shared__ float sm[];
    Ctx cx;
    cx.sva = sm + O_VA;  cx.szp = sm + O_ZP;  cx.sdch = (__half*)(sm + O_DCH);
    cx.sd = sm + O_D;    cx.sc = sm + O_C;    cx.sbeta = sm + O_BETA;
    cx.spx2 = sm + O_PX2; cx.syp = sm + O_YP; cx.sW2 = sm + O_W2;
    cx.sWx = sm + O_WX;  cx.sbl = sm + O_BL;  cx.ssb = sm + O_SSB; cx.sq = sm + O_SQ;
    cx.swhf = (uint2*)(sm + O_WHF);

    int tid = threadIdx.x, lane = tid & 31, wid = tid >> 5;
    int b0 = blockIdx.x * GMAX;
    if (b0 >= BSZ) return;
    int nb = min(GMAX, BSZ - b0);

    if (tid < 128) cx.sW2[tid] = W2[tid];
    if (tid < 512) { cx.sWx[tid] = Wx[tid]; cx.sbl[tid] = bl[tid]; }
    if (tid < 16) cx.ssb[tid] = 0.f;
    if (tid >= 16 && tid < 24) cx.sq[tid - 16] = 0.f;
    for (int i = tid; i < 16 * DCS; i += THREADS) cx.sdch[i] = __float2half(0.f);
    for (int i = tid; i < 16384; i += THREADS) cx.swhf[i] = g_whf[i];
    __syncthreads();
    if (tid < GMAX * 128) {
        int b = tid >> 7, k = tid & 127;
        bool ok = (b < nb) && (k < T1);
        cx.spx2[tid] = ok ? g_px2[(b0 + b) * T1 + k] : 0.f;
        cx.syp[tid]  = ok ? yprev[(size_t)(b0 + b) * T1 + k] : 0.f;
        float x00 = (b < nb) ? X[(size_t)(b0 + b) * T1 * HE] : 0.f;
        cx.sd[tid] = x00; cx.sc[tid] = x00;
        __half xh = __float2half(x00);
        cx.sdch[b * DCS + k] = xh;
        cx.sdch[b * DCS + 128 + k] = xh;
    }
    float b2v  = b2[0];
    float bfcv = bfc[0];
    float wfcy = Wfc[HE];
    __syncthreads();
    if (wid < nb) {
        const float* p = cx.spx2 + wid * 128;
        float v = p[lane] + p[lane+32] + p[lane+64] + p[lane+96];
        #pragma unroll
        for (int m = 16; m; m >>= 1) v += __shfl_xor_sync(0xffffffffu, v, m);
        if (lane == 0) cx.sq[wid] = v;
    }
    __syncthreads();

    unsigned dch_saddr = (unsigned)__cvta_generic_to_shared(cx.sdch)
                       + (lane % 16) * (DCS * 2) + (lane >> 4) * 16;
    int w = wid - 16;
    int row = lane >> 2;

    for (int t = 0; t < T1; t++) {
        // ---- Region 1: A-mma by warps 16-31 ----
        if (w >= 0) {
            uint2 bw[16];
            #pragma unroll
            for (int kt = 0; kt < 16; kt++) bw[kt] = g_w1f[(kt*16 + w)*32 + lane];
            float d0 = 0.f, d1 = 0.f, d2 = 0.f, d3 = 0.f;
            #pragma unroll
            for (int kt = 0; kt < 16; kt++) {
                unsigned a0, a1, a2, a3;
                LDSM4(a0, a1, a2, a3, dch_saddr + kt * 32);
                MMA16816(d0, d1, d2, d3, a0, a1, a2, a3, bw[kt].x, bw[kt].y);
            }
            if (row < GMAX)
                *(float2*)(cx.sva + row * SVAS + w * 8 + (lane & 3) * 2) = make_float2(d0, d1);
        }
        __syncthreads();

        // ---- Region 2: B (warps 0-13) || C-mma (warps 16-31, frags from smem) ----
        {
            bool last = (t == T1 - 1);
            if (wid < 14) {
                int b = wid >> 1;
                if (b < nb) phaseB(cx, b0, b, wid & 1, lane, last, b2v);
            } else if (w >= 0) {
                float acc[16];
                #pragma unroll
                for (int i = 0; i < 16; i++) acc[i] = 0.f;
                const uint2* whs = cx.swhf + (w * 4) * 32 + lane;
                #pragma unroll
                for (int kt = 0; kt < 8; kt++) {
                    unsigned a0, a1, a2, a3;
                    LDSM4(a0, a1, a2, a3, dch_saddr + kt * 32);
                    uint2 f0 = whs[kt*2048];
                    uint2 f1 = whs[kt*2048 + 32];
                    uint2 f2 = whs[kt*2048 + 64];
                    uint2 f3 = whs[kt*2048 + 96];
                    MMA16816(acc[0],  acc[1],  acc[2],  acc[3],  a0,a1,a2,a3, f0.x, f0.y);
                    MMA16816(acc[4],  acc[5],  acc[6],  acc[7],  a0,a1,a2,a3, f1.x, f1.y);
                    MMA16816(acc[8],  acc[9],  acc[10], acc[11], a0,a1,a2,a3, f2.x, f2.y);
                    MMA16816(acc[12], acc[13], acc[14], acc[15], a0,a1,a2,a3, f3.x, f3.y);
                }
                if (row < GMAX) {
                    float* zb = cx.szp + row * ZPS + w * 32 + (lane & 3) * 2;
                    #pragma unroll
                    for (int nt = 0; nt < 4; nt++)
                        *(float2*)(zb + nt * 8) = make_float2(acc[nt*4], acc[nt*4+1]);
                }
            }
        }
        __syncthreads();

        // ---- Region 3: D — gates, state update ----
        if (tid < GMAX * 128) {
            int b = tid >> 7, k = tid & 127;
            float s  = cx.ssb[2*b] + cx.ssb[2*b+1] + b2v * cx.sq[b];
            float yt = fmaf(cx.syp[b*128 + t], wfcy, s + bfcv);
            const float* zb = cx.szp + b * ZPS;
            float zi = fmaf(yt, cx.sWx[k],     zb[k]     + cx.sbl[k]);
            float zf = fmaf(yt, cx.sWx[128+k], zb[128+k] + cx.sbl[128+k]);
            float zg = fmaf(yt, cx.sWx[256+k], zb[256+k] + cx.sbl[256+k]);
            float zo = fmaf(yt, cx.sWx[384+k], zb[384+k] + cx.sbl[384+k]);
            float cn = fmaf(sig_ap(zf), cx.sc[tid], sig_ap(zi) * tanh_ap(zg));
            float dn = sig_ap(zo) * tanh_ap(cn);
            cx.sc[tid] = cn;
            cx.sd[tid] = dn;
            cx.sdch[b * DCS + k]       = __float2half(dn);
            cx.sdch[b * DCS + 128 + k] = __float2half(cn);
        }
        __syncthreads();
    }

    // ---- Epilogue ----
    if (wid < nb) {
        int b = wid;
        const float4* Xb = (const float4*)(X + (size_t)(b0 + b) * T1 * HE);
        float cxx = 0.f, cy = 0.f, cz = 0.f, cw = 0.f;
        for (int tp = 0; tp < T1; tp++) {
            float bb = cx.sbeta[b*128 + tp];
            float4 xv = Xb[tp*32 + lane];
            cxx = fmaf(bb, xv.x, cxx); cy = fmaf(bb, xv.y, cy);
            cz  = fmaf(bb, xv.z, cz);  cw = fmaf(bb, xv.w, cw);
        }
        float4 wfc2 = ((const float4*)(Wf + 128))[lane];
        float4 wfd  = ((const float4*)Wf)[lane];
        float4 dv   = ((const float4*)(cx.sd + b*128))[lane];
        float r = cxx*wfc2.x + cy*wfc2.y + cz*wfc2.z + cw*wfc2.w;
        r = fmaf(dv.x, wfd.x, r); r = fmaf(dv.y, wfd.y, r);
        r = fmaf(dv.z, wfd.z, r); r = fmaf(dv.w, wfd.w, r);
        #pragma unroll
        for (int m = 16; m; m >>= 1) r += __shfl_xor_sync(0xffffffffu, r, m);
        if (lane == 0) out[b0 + b] = r + bf[0];
    }
}

extern "C" void kernel_launch(void* const* d_in, const int* in_sizes, int n_in,
                              void* d_out, int out_size)
{
    const float* X    = (const float*)d_in[0];
    const float* yprev= (const float*)d_in[1];
    const float* W1   = (const float*)d_in[2];
    const float* b1   = (const float*)d_in[3];
    const float* W2   = (const float*)d_in[4];
    const float* b2   = (const float*)d_in[5];
    const float* Wfc  = (const float*)d_in[6];
    const float* bfc  = (const float*)d_in[7];
    const float* Wx   = (const float*)d_in[8];
    const float* Wh   = (const float*)d_in[9];
    const float* bl   = (const float*)d_in[10];
    const float* Wf   = (const float*)d_in[11];
    const float* bf   = (const float*)d_in[12];
    float* out = (float*)d_out;

    cudaFuncSetAttribute(decoder_kernel, cudaFuncAttributeMaxDynamicSharedMemorySize, MAIN_SMEM);

    pack_kernel<<<112, 256>>>(W1, Wh);
    prex_kernel<<<BSZ, 256>>>(X, b1, Wfc);
    decoder_kernel<<<NCTA, THREADS, MAIN_SMEM>>>(X, yprev, W1, W2, b2, Wfc, bfc,
                                                 Wx, Wh, bl, Wf, bf, out);
}

// round 14
// speedup vs baseline: 2.0242x; 1.0180x over previous
#include <cuda_runtime.h>
#include <cuda_fp16.h>

#define BSZ 1024
#define T1  127
#define TP  128
#define HD  128
#define HE  128
#define ZD  512
#define GMAX 7
#define NCTA 147
#define THREADS 1024
#define SVAS 132
#define ZPS  516
#define DCS  264

__device__ __half g_prex[(size_t)BSZ * TP * HE];   // 33.5 MB, L2-resident
__device__ float  g_px2[BSZ * T1];
__device__ uint2  g_whf[8 * 64 * 32];              // Wh  fragment-packed fp16
__device__ uint2  g_w1f[16 * 16 * 32];             // W1(d|c) fragment-packed
__device__ uint2  g_w1xf[8 * 16 * 32];             // W1_x fragment-packed

static __device__ __forceinline__ float tanh_ap(float x){
    float r; asm("tanh.approx.f32 %0, %1;" : "=f"(r) : "f"(x)); return r;
}
static __device__ __forceinline__ float sig_ap(float x){
    return fmaf(0.5f, tanh_ap(0.5f * x), 0.5f);
}
static __device__ __forceinline__ unsigned tanh2_ap(unsigned x){
    unsigned r; asm("tanh.approx.f16x2 %0, %1;" : "=r"(r) : "r"(x)); return r;
}
static __device__ __forceinline__ unsigned h2u(__half2 h){
    union { __half2 h; unsigned u; } v; v.h = h; return v.u;
}
static __device__ __forceinline__ __half2 u2h(unsigned u){
    union { __half2 h; unsigned u; } v; v.u = u; return v.h;
}

#define MMA16816(d0,d1,d2,d3,a0,a1,a2,a3,b0,b1) \
    asm volatile("mma.sync.aligned.m16n8k16.row.col.f32.f16.f16.f32 " \
        "{%0,%1,%2,%3}, {%4,%5,%6,%7}, {%8,%9}, {%0,%1,%2,%3};" \
        : "+f"(d0),"+f"(d1),"+f"(d2),"+f"(d3) \
        : "r"(a0),"r"(a1),"r"(a2),"r"(a3),"r"(b0),"r"(b1))

#define LDSM4(a0,a1,a2,a3,addr) \
    asm volatile("ldmatrix.sync.aligned.m8n8.x4.shared.b16 {%0,%1,%2,%3}, [%4];" \
        : "=r"(a0),"=r"(a1),"=r"(a2),"=r"(a3) : "r"(addr))

// ---------------------------------------------------------------------------
// Pack kernel: fragment-pack Wh, W1dc, W1x
// ---------------------------------------------------------------------------
__global__ void __launch_bounds__(256, 1)
pack_kernel(const float* __restrict__ W1, const float* __restrict__ Wh)
{
    int bb = blockIdx.x, tid = threadIdx.x;
    if (bb < 64) {
        int idx = bb * 256 + tid;
        int kt = idx >> 11, nt = (idx >> 5) & 63, L = idx & 31;
        int kb = kt * 16 + (L & 3) * 2, n = nt * 8 + (L >> 2);
        g_whf[idx] = make_uint2(
            h2u(__floats2half2_rn(Wh[(size_t)kb*ZD + n],     Wh[(size_t)(kb+1)*ZD + n])),
            h2u(__floats2half2_rn(Wh[(size_t)(kb+8)*ZD + n], Wh[(size_t)(kb+9)*ZD + n])));
    } else if (bb < 96) {
        int idx = (bb - 64) * 256 + tid;
        int kt = idx >> 9, nt = (idx >> 5) & 15, L = idx & 31;
        int kb = kt * 16 + (L & 3) * 2, n = nt * 8 + (L >> 2);
        g_w1f[idx] = make_uint2(
            h2u(__floats2half2_rn(W1[kb*HE + n],     W1[(kb+1)*HE + n])),
            h2u(__floats2half2_rn(W1[(kb+8)*HE + n], W1[(kb+9)*HE + n])));
    } else {
        int idx = (bb - 96) * 256 + tid;
        int kt = idx >> 9, nt = (idx >> 5) & 15, L = idx & 31;
        int kb = 2*HD + kt * 16 + (L & 3) * 2, n = nt * 8 + (L >> 2);
        g_w1xf[idx] = make_uint2(
            h2u(__floats2half2_rn(W1[kb*HE + n],     W1[(kb+1)*HE + n])),
            h2u(__floats2half2_rn(W1[(kb+8)*HE + n], W1[(kb+9)*HE + n])));
    }
}

// ---------------------------------------------------------------------------
// Prepass: pre_x = X@W1_x + b1 via tensor cores; px2
// ---------------------------------------------------------------------------
__global__ void __launch_bounds__(256, 1)
prex_kernel(const float* __restrict__ X, const float* __restrict__ b1,
            const float* __restrict__ Wfc)
{
    __shared__ __half sXh[128 * 136];
    int b = blockIdx.x;
    int tid = threadIdx.x, lane = tid & 31, wid = tid >> 5;
    const float* Xb = X + (size_t)b * T1 * HE;

    for (int i = tid; i < T1 * HE; i += 256) {
        int row = i >> 7, col = i & 127;
        sXh[row * 136 + col] = __float2half(Xb[i]);
    }
    if (tid < 128) sXh[127 * 136 + tid] = __float2half(0.f);
    __syncthreads();

    float4 wf = ((const float4*)Wfc)[lane];
    for (int t = wid; t < T1; t += 8) {
        float4 x = ((const float4*)(Xb + t * HE))[lane];
        float p = x.x * wf.x + x.y * wf.y + x.z * wf.z + x.w * wf.w;
        #pragma unroll
        for (int m = 16; m; m >>= 1) p += __shfl_xor_sync(0xffffffffu, p, m);
        if (lane == 0) g_px2[b * T1 + t] = p;
    }

    unsigned sa = (unsigned)__cvta_generic_to_shared(sXh)
                + (wid * 16 + (lane & 15)) * 272 + (lane >> 4) * 16;
    unsigned af[8][4];
    #pragma unroll
    for (int kt = 0; kt < 8; kt++)
        LDSM4(af[kt][0], af[kt][1], af[kt][2], af[kt][3], sa + kt * 32);

    int t0 = wid * 16 + (lane >> 2);
    #pragma unroll 1
    for (int nt = 0; nt < 16; nt++) {
        float d0 = 0.f, d1 = 0.f, d2 = 0.f, d3 = 0.f;
        #pragma unroll
        for (int kt = 0; kt < 8; kt++) {
            uint2 bw = g_w1xf[(kt*16 + nt)*32 + lane];
            MMA16816(d0, d1, d2, d3, af[kt][0], af[kt][1], af[kt][2], af[kt][3],
                     bw.x, bw.y);
        }
        int e0 = nt * 8 + (lane & 3) * 2;
        float2 bb = *(const float2*)(b1 + e0);
        *(__half2*)(g_prex + ((size_t)b * TP + t0) * HE + e0) =
            __floats2half2_rn(d0 + bb.x, d1 + bb.y);
        *(__half2*)(g_prex + ((size_t)b * TP + t0 + 8) * HE + e0) =
            __floats2half2_rn(d2 + bb.x, d3 + bb.y);
    }
}

// ---------------------------------------------------------------------------
// Main kernel: A+C mma in region 1 (warps 16-31); B on 28 warps in region 2
// ---------------------------------------------------------------------------
#define O_VA   0                        // [7][132] = 924
#define O_ZP   924                      // [7][516] = 3612
#define O_DCH  (O_ZP + 3612)            // [16][264] half = 2112 floats
#define O_D    (O_DCH + 2112)           // 896
#define O_C    (O_D + 896)              // 896
#define O_BETA (O_C + 896)              // 896
#define O_PX2  (O_BETA + 896)           // 896
#define O_YP   (O_PX2 + 896)            // 896
#define O_W2   (O_YP + 896)             // 128
#define O_WX   (O_W2 + 128)             // 512
#define O_BL   (O_WX + 512)             // 512
#define O_SSB  (O_BL + 512)             // 32
#define O_SQ   (O_SSB + 32)             // 8
#define O_WHF  (O_SQ + 8)               // 16384 uint2 = 32768 floats
#define MAIN_FLOATS (O_WHF + 32768)
#define MAIN_SMEM (MAIN_FLOATS * 4)     // ~180.4 KB

struct Ctx {
    float* sva; float* szp; __half* sdch; float* sd; float* sc; float* sbeta;
    float* spx2; float* syp; float* sW2; float* sWx; float* sbl; float* ssb;
    float* sq; uint2* swhf;
};

// Phase B quarter: one warp per (b, q); 32 timesteps
static __device__ __forceinline__ void phaseB(const Ctx& cx, int b0, int b, int q,
                                              int lane, bool last, float b2v)
{
    float4 vr = *(const float4*)(cx.sva + b * SVAS + lane * 4);
    float4 w2r = ((const float4*)cx.sW2)[lane];
    __half2 vr01 = __floats2half2_rn(vr.x, vr.y);
    __half2 vr23 = __floats2half2_rn(vr.z, vr.w);
    __half2 w01  = __floats2half2_rn(w2r.x, w2r.y);
    __half2 w23  = __floats2half2_rn(w2r.z, w2r.w);

    const uint2* pxb = ((const uint2*)(g_prex + (size_t)(b0 + b) * TP * HE)) + lane;
    const float* px2b = cx.spx2 + b * 128;
    float s_l = 0.f;
    int tp0 = q * 32;

    uint2 c0 = pxb[(tp0+0)*32], c1 = pxb[(tp0+1)*32];
    uint2 c2 = pxb[(tp0+2)*32], c3 = pxb[(tp0+3)*32];

    #pragma unroll 1
    for (int tc = 0; tc < 32; tc += 4) {
        int tp = tp0 + tc;
        int tn = (tc + 4 < 32) ? tp + 4 : tp;
        uint2 n0 = pxb[(tn+0)*32], n1 = pxb[(tn+1)*32];
        uint2 n2 = pxb[(tn+2)*32], n3 = pxb[(tn+3)*32];

        __half2 h0a = u2h(tanh2_ap(h2u(__hadd2(u2h(c0.x), vr01))));
        __half2 h0b = u2h(tanh2_ap(h2u(__hadd2(u2h(c0.y), vr23))));
        __half2 h1a = u2h(tanh2_ap(h2u(__hadd2(u2h(c1.x), vr01))));
        __half2 h1b = u2h(tanh2_ap(h2u(__hadd2(u2h(c1.y), vr23))));
        __half2 h2a = u2h(tanh2_ap(h2u(__hadd2(u2h(c2.x), vr01))));
        __half2 h2b = u2h(tanh2_ap(h2u(__hadd2(u2h(c2.y), vr23))));
        __half2 h3a = u2h(tanh2_ap(h2u(__hadd2(u2h(c3.x), vr01))));
        __half2 h3b = u2h(tanh2_ap(h2u(__hadd2(u2h(c3.y), vr23))));

        __half2 p0 = __hfma2(h0b, w23, __hmul2(h0a, w01));
        __half2 p1 = __hfma2(h1b, w23, __hmul2(h1a, w01));
        __half2 p2 = __hfma2(h2b, w23, __hmul2(h2a, w01));
        __half2 p3 = __hfma2(h3b, w23, __hmul2(h3a, w01));
        float2 q0 = __half22float2(p0);
        float2 q1 = __half22float2(p1);
        float2 q2 = __half22float2(p2);
        float2 q3 = __half22float2(p3);
        float pl0 = q0.x + q0.y, pl1 = q1.x + q1.y;
        float pl2 = q2.x + q2.y, pl3 = q3.x + q3.y;

        s_l = fmaf(pl0, px2b[tp+0], s_l);
        s_l = fmaf(pl1, px2b[tp+1], s_l);
        s_l = fmaf(pl2, px2b[tp+2], s_l);
        s_l = fmaf(pl3, px2b[tp+3], s_l);

        if (last) {
            float r0 = pl0, r1 = pl1, r2 = pl2, r3 = pl3;
            #pragma unroll
            for (int m = 16; m; m >>= 1) {
                r0 += __shfl_xor_sync(0xffffffffu, r0, m);
                r1 += __shfl_xor_sync(0xffffffffu, r1, m);
                r2 += __shfl_xor_sync(0xffffffffu, r2, m);
                r3 += __shfl_xor_sync(0xffffffffu, r3, m);
            }
            if (lane == 0) {
                cx.sbeta[b*128 + tp+0] = r0 + b2v;
                cx.sbeta[b*128 + tp+1] = r1 + b2v;
                cx.sbeta[b*128 + tp+2] = r2 + b2v;
                cx.sbeta[b*128 + tp+3] = r3 + b2v;
            }
        }
        c0 = n0; c1 = n1; c2 = n2; c3 = n3;
    }
    #pragma unroll
    for (int m = 16; m; m >>= 1) s_l += __shfl_xor_sync(0xffffffffu, s_l, m);
    if (lane == 0) cx.ssb[4*b + q] = s_l;
}

__global__ void __launch_bounds__(THREADS, 1)
decoder_kernel(const float* __restrict__ X, const float* __restrict__ yprev,
               const float* __restrict__ W1, const float* __restrict__ W2,
               const float* __restrict__ b2, const float* __restrict__ Wfc,
               const float* __restrict__ bfc, const float* __restrict__ Wx,
               const float* __restrict__ Wh, const float* __restrict__ bl,
               const float* __restrict__ Wf, const float* __restrict__ bf,
               float* __restrict__ out)
{
    extern __shared__ float sm[];
    Ctx cx;
    cx.sva = sm + O_VA;  cx.szp = sm + O_ZP;  cx.sdch = (__half*)(sm + O_DCH);
    cx.sd = sm + O_D;    cx.sc = sm + O_C;    cx.sbeta = sm + O_BETA;
    cx.spx2 = sm + O_PX2; cx.syp = sm + O_YP; cx.sW2 = sm + O_W2;
    cx.sWx = sm + O_WX;  cx.sbl = sm + O_BL;  cx.ssb = sm + O_SSB; cx.sq = sm + O_SQ;
    cx.swhf = (uint2*)(sm + O_WHF);

    int tid = threadIdx.x, lane = tid & 31, wid = tid >> 5;
    int b0 = blockIdx.x * GMAX;
    if (b0 >= BSZ) return;
    int nb = min(GMAX, BSZ - b0);

    if (tid < 128) cx.sW2[tid] = W2[tid];
    if (tid < 512) { cx.sWx[tid] = Wx[tid]; cx.sbl[tid] = bl[tid]; }
    if (tid < 32) cx.ssb[tid] = 0.f;
    if (tid >= 32 && tid < 40) cx.sq[tid - 32] = 0.f;
    for (int i = tid; i < 16 * DCS; i += THREADS) cx.sdch[i] = __float2half(0.f);
    for (int i = tid; i < 16384; i += THREADS) cx.swhf[i] = g_whf[i];
    __syncthreads();
    if (tid < GMAX * 128) {
        int b = tid >> 7, k = tid & 127;
        bool ok = (b < nb) && (k < T1);
        cx.spx2[tid] = ok ? g_px2[(b0 + b) * T1 + k] : 0.f;
        cx.syp[tid]  = ok ? yprev[(size_t)(b0 + b) * T1 + k] : 0.f;
        float x00 = (b < nb) ? X[(size_t)(b0 + b) * T1 * HE] : 0.f;
        cx.sd[tid] = x00; cx.sc[tid] = x00;
        __half xh = __float2half(x00);
        cx.sdch[b * DCS + k] = xh;
        cx.sdch[b * DCS + 128 + k] = xh;
    }
    float b2v  = b2[0];
    float bfcv = bfc[0];
    float wfcy = Wfc[HE];
    __syncthreads();
    if (wid < nb) {
        const float* p = cx.spx2 + wid * 128;
        float v = p[lane] + p[lane+32] + p[lane+64] + p[lane+96];
        #pragma unroll
        for (int m = 16; m; m >>= 1) v += __shfl_xor_sync(0xffffffffu, v, m);
        if (lane == 0) cx.sq[wid] = v;
    }
    __syncthreads();

    unsigned dch_saddr = (unsigned)__cvta_generic_to_shared(cx.sdch)
                       + (lane % 16) * (DCS * 2) + (lane >> 4) * 16;
    int w = wid - 16;
    int row = lane >> 2;

    for (int t = 0; t < T1; t++) {
        // ---- Region 1 (warps 16-31): A-mma then C-mma ----
        if (w >= 0) {
            {   // A
                uint2 bw[16];
                #pragma unroll
                for (int kt = 0; kt < 16; kt++) bw[kt] = g_w1f[(kt*16 + w)*32 + lane];
                float d0 = 0.f, d1 = 0.f, d2 = 0.f, d3 = 0.f;
                #pragma unroll
                for (int kt = 0; kt < 16; kt++) {
                    unsigned a0, a1, a2, a3;
                    LDSM4(a0, a1, a2, a3, dch_saddr + kt * 32);
                    MMA16816(d0, d1, d2, d3, a0, a1, a2, a3, bw[kt].x, bw[kt].y);
                }
                if (row < GMAX)
                    *(float2*)(cx.sva + row * SVAS + w * 8 + (lane & 3) * 2) = make_float2(d0, d1);
            }
            {   // C (frags from smem)
                float acc[16];
                #pragma unroll
                for (int i = 0; i < 16; i++) acc[i] = 0.f;
                const uint2* whs = cx.swhf + (w * 4) * 32 + lane;
                #pragma unroll
                for (int kt = 0; kt < 8; kt++) {
                    unsigned a0, a1, a2, a3;
                    LDSM4(a0, a1, a2, a3, dch_saddr + kt * 32);
                    uint2 f0 = whs[kt*2048];
                    uint2 f1 = whs[kt*2048 + 32];
                    uint2 f2 = whs[kt*2048 + 64];
                    uint2 f3 = whs[kt*2048 + 96];
                    MMA16816(acc[0],  acc[1],  acc[2],  acc[3],  a0,a1,a2,a3, f0.x, f0.y);
                    MMA16816(acc[4],  acc[5],  acc[6],  acc[7],  a0,a1,a2,a3, f1.x, f1.y);
                    MMA16816(acc[8],  acc[9],  acc[10], acc[11], a0,a1,a2,a3, f2.x, f2.y);
                    MMA16816(acc[12], acc[13], acc[14], acc[15], a0,a1,a2,a3, f3.x, f3.y);
                }
                if (row < GMAX) {
                    float* zb = cx.szp + row * ZPS + w * 32 + (lane & 3) * 2;
                    #pragma unroll
                    for (int nt = 0; nt < 4; nt++)
                        *(float2*)(zb + nt * 8) = make_float2(acc[nt*4], acc[nt*4+1]);
                }
            }
        }
        __syncthreads();

        // ---- Region 2: B on 28 warps (4 per batch) ----
        {
            bool last = (t == T1 - 1);
            if (wid < 28) {
                int b = wid >> 2;
                if (b < nb) phaseB(cx, b0, b, wid & 3, lane, last, b2v);
            }
        }
        __syncthreads();

        // ---- Region 3: D — gates, state update ----
        if (tid < GMAX * 128) {
            int b = tid >> 7, k = tid & 127;
            float s  = cx.ssb[4*b] + cx.ssb[4*b+1] + cx.ssb[4*b+2] + cx.ssb[4*b+3]
                     + b2v * cx.sq[b];
            float yt = fmaf(cx.syp[b*128 + t], wfcy, s + bfcv);
            const float* zb = cx.szp + b * ZPS;
            float zi = fmaf(yt, cx.sWx[k],     zb[k]     + cx.sbl[k]);
            float zf = fmaf(yt, cx.sWx[128+k], zb[128+k] + cx.sbl[128+k]);
            float zg = fmaf(yt, cx.sWx[256+k], zb[256+k] + cx.sbl[256+k]);
            float zo = fmaf(yt, cx.sWx[384+k], zb[384+k] + cx.sbl[384+k]);
            float cn = fmaf(sig_ap(zf), cx.sc[tid], sig_ap(zi) * tanh_ap(zg));
            float dn = sig_ap(zo) * tanh_ap(cn);
            cx.sc[tid] = cn;
            cx.sd[tid] = dn;
            cx.sdch[b * DCS + k]       = __float2half(dn);
            cx.sdch[b * DCS + 128 + k] = __float2half(cn);
        }
        __syncthreads();
    }

    // ---- Epilogue ----
    if (wid < nb) {
        int b = wid;
        const float4* Xb = (const float4*)(X + (size_t)(b0 + b) * T1 * HE);
        float cxx = 0.f, cy = 0.f, cz = 0.f, cw = 0.f;
        for (int tp = 0; tp < T1; tp++) {
            float bb = cx.sbeta[b*128 + tp];
            float4 xv = Xb[tp*32 + lane];
            cxx = fmaf(bb, xv.x, cxx); cy = fmaf(bb, xv.y, cy);
            cz  = fmaf(bb, xv.z, cz);  cw = fmaf(bb, xv.w, cw);
        }
        float4 wfc2 = ((const float4*)(Wf + 128))[lane];
        float4 wfd  = ((const float4*)Wf)[lane];
        float4 dv   = ((const float4*)(cx.sd + b*128))[lane];
        float r = cxx*wfc2.x + cy*wfc2.y + cz*wfc2.z + cw*wfc2.w;
        r = fmaf(dv.x, wfd.x, r); r = fmaf(dv.y, wfd.y, r);
        r = fmaf(dv.z, wfd.z, r); r = fmaf(dv.w, wfd.w, r);
        #pragma unroll
        for (int m = 16; m; m >>= 1) r += __shfl_xor_sync(0xffffffffu, r, m);
        if (lane == 0) out[b0 + b] = r + bf[0];
    }
}

extern "C" void kernel_launch(void* const* d_in, const int* in_sizes, int n_in,
                              void* d_out, int out_size)
{
    const float* X    = (const float*)d_in[0];
    const float* yprev= (const float*)d_in[1];
    const float* W1   = (const float*)d_in[2];
    const float* b1   = (const float*)d_in[3];
    const float* W2   = (const float*)d_in[4];
    const float* b2   = (const float*)d_in[5];
    const float* Wfc  = (const float*)d_in[6];
    const float* bfc  = (const float*)d_in[7];
    const float* Wx   = (const float*)d_in[8];
    const float* Wh   = (const float*)d_in[9];
    const float* bl   = (const float*)d_in[10];
    const float* Wf   = (const float*)d_in[11];
    const float* bf   = (const float*)d_in[12];
    float* out = (float*)d_out;

    cudaFuncSetAttribute(decoder_kernel, cudaFuncAttributeMaxDynamicSharedMemorySize, MAIN_SMEM);

    pack_kernel<<<112, 256>>>(W1, Wh);
    prex_kernel<<<BSZ, 256>>>(X, b1, Wfc);
    decoder_kernel<<<NCTA, THREADS, MAIN_SMEM>>>(X, yprev, W1, W2, b2, Wfc, bfc,
                                                 Wx, Wh, bl, Wf, bf, out);
}

// round 15
// speedup vs baseline: 2.0489x; 1.0122x over previous
#include <cuda_runtime.h>
#include <cuda_fp16.h>

#define BSZ 1024
#define T1  127
#define TP  128
#define HD  128
#define HE  128
#define ZD  512
#define GMAX 7
#define NCTA 147
#define THREADS 896
#define SVAS 132
#define ZPS  516
#define DCS  264

__device__ __half g_prex[(size_t)BSZ * TP * HE];   // 33.5 MB, L2-resident
__device__ float  g_px2[BSZ * T1];
__device__ uint2  g_whf[8 * 64 * 32];              // Wh  fragment-packed fp16
__device__ uint2  g_w1f[16 * 16 * 32];             // W1(d|c) fragment-packed
__device__ uint2  g_w1xf[8 * 16 * 32];             // W1_x fragment-packed

static __device__ __forceinline__ float tanh_ap(float x){
    float r; asm("tanh.approx.f32 %0, %1;" : "=f"(r) : "f"(x)); return r;
}
static __device__ __forceinline__ float sig_ap(float x){
    return fmaf(0.5f, tanh_ap(0.5f * x), 0.5f);
}
static __device__ __forceinline__ unsigned tanh2_ap(unsigned x){
    unsigned r; asm("tanh.approx.f16x2 %0, %1;" : "=r"(r) : "r"(x)); return r;
}
static __device__ __forceinline__ unsigned h2u(__half2 h){
    union { __half2 h; unsigned u; } v; v.h = h; return v.u;
}
static __device__ __forceinline__ __half2 u2h(unsigned u){
    union { __half2 h; unsigned u; } v; v.u = u; return v.h;
}

#define MMA16816(d0,d1,d2,d3,a0,a1,a2,a3,b0,b1) \
    asm volatile("mma.sync.aligned.m16n8k16.row.col.f32.f16.f16.f32 " \
        "{%0,%1,%2,%3}, {%4,%5,%6,%7}, {%8,%9}, {%0,%1,%2,%3};" \
        : "+f"(d0),"+f"(d1),"+f"(d2),"+f"(d3) \
        : "r"(a0),"r"(a1),"r"(a2),"r"(a3),"r"(b0),"r"(b1))

#define LDSM4(a0,a1,a2,a3,addr) \
    asm volatile("ldmatrix.sync.aligned.m8n8.x4.shared.b16 {%0,%1,%2,%3}, [%4];" \
        : "=r"(a0),"=r"(a1),"=r"(a2),"=r"(a3) : "r"(addr))

// ---------------------------------------------------------------------------
// Pack kernel: fragment-pack Wh, W1dc, W1x
// ---------------------------------------------------------------------------
__global__ void __launch_bounds__(256, 1)
pack_kernel(const float* __restrict__ W1, const float* __restrict__ Wh)
{
    int bb = blockIdx.x, tid = threadIdx.x;
    if (bb < 64) {
        int idx = bb * 256 + tid;
        int kt = idx >> 11, nt = (idx >> 5) & 63, L = idx & 31;
        int kb = kt * 16 + (L & 3) * 2, n = nt * 8 + (L >> 2);
        g_whf[idx] = make_uint2(
            h2u(__floats2half2_rn(Wh[(size_t)kb*ZD + n],     Wh[(size_t)(kb+1)*ZD + n])),
            h2u(__floats2half2_rn(Wh[(size_t)(kb+8)*ZD + n], Wh[(size_t)(kb+9)*ZD + n])));
    } else if (bb < 96) {
        int idx = (bb - 64) * 256 + tid;
        int kt = idx >> 9, nt = (idx >> 5) & 15, L = idx & 31;
        int kb = kt * 16 + (L & 3) * 2, n = nt * 8 + (L >> 2);
        g_w1f[idx] = make_uint2(
            h2u(__floats2half2_rn(W1[kb*HE + n],     W1[(kb+1)*HE + n])),
            h2u(__floats2half2_rn(W1[(kb+8)*HE + n], W1[(kb+9)*HE + n])));
    } else {
        int idx = (bb - 96) * 256 + tid;
        int kt = idx >> 9, nt = (idx >> 5) & 15, L = idx & 31;
        int kb = 2*HD + kt * 16 + (L & 3) * 2, n = nt * 8 + (L >> 2);
        g_w1xf[idx] = make_uint2(
            h2u(__floats2half2_rn(W1[kb*HE + n],     W1[(kb+1)*HE + n])),
            h2u(__floats2half2_rn(W1[(kb+8)*HE + n], W1[(kb+9)*HE + n])));
    }
}

// ---------------------------------------------------------------------------
// Prepass: pre_x = X@W1_x + b1 via tensor cores; px2
// ---------------------------------------------------------------------------
__global__ void __launch_bounds__(256, 1)
prex_kernel(const float* __restrict__ X, const float* __restrict__ b1,
            const float* __restrict__ Wfc)
{
    __shared__ __half sXh[128 * 136];
    int b = blockIdx.x;
    int tid = threadIdx.x, lane = tid & 31, wid = tid >> 5;
    const float* Xb = X + (size_t)b * T1 * HE;

    for (int i = tid; i < T1 * HE; i += 256) {
        int row = i >> 7, col = i & 127;
        sXh[row * 136 + col] = __float2half(Xb[i]);
    }
    if (tid < 128) sXh[127 * 136 + tid] = __float2half(0.f);
    __syncthreads();

    float4 wf = ((const float4*)Wfc)[lane];
    for (int t = wid; t < T1; t += 8) {
        float4 x = ((const float4*)(Xb + t * HE))[lane];
        float p = x.x * wf.x + x.y * wf.y + x.z * wf.z + x.w * wf.w;
        #pragma unroll
        for (int m = 16; m; m >>= 1) p += __shfl_xor_sync(0xffffffffu, p, m);
        if (lane == 0) g_px2[b * T1 + t] = p;
    }

    unsigned sa = (unsigned)__cvta_generic_to_shared(sXh)
                + (wid * 16 + (lane & 15)) * 272 + (lane >> 4) * 16;
    unsigned af[8][4];
    #pragma unroll
    for (int kt = 0; kt < 8; kt++)
        LDSM4(af[kt][0], af[kt][1], af[kt][2], af[kt][3], sa + kt * 32);

    int t0 = wid * 16 + (lane >> 2);
    #pragma unroll 1
    for (int nt = 0; nt < 16; nt++) {
        float d0 = 0.f, d1 = 0.f, d2 = 0.f, d3 = 0.f;
        #pragma unroll
        for (int kt = 0; kt < 8; kt++) {
            uint2 bw = g_w1xf[(kt*16 + nt)*32 + lane];
            MMA16816(d0, d1, d2, d3, af[kt][0], af[kt][1], af[kt][2], af[kt][3],
                     bw.x, bw.y);
        }
        int e0 = nt * 8 + (lane & 3) * 2;
        float2 bb = *(const float2*)(b1 + e0);
        *(__half2*)(g_prex + ((size_t)b * TP + t0) * HE + e0) =
            __floats2half2_rn(d0 + bb.x, d1 + bb.y);
        *(__half2*)(g_prex + ((size_t)b * TP + t0 + 8) * HE + e0) =
            __floats2half2_rn(d2 + bb.x, d3 + bb.y);
    }
}

// ---------------------------------------------------------------------------
// Main kernel: 896 threads; mma warps 12-27; B on all 28 warps
// ---------------------------------------------------------------------------
#define O_VA   0                        // [7][132] = 924
#define O_ZP   924                      // [7][516] = 3612
#define O_DCH  (O_ZP + 3612)            // [16][264] half = 2112 floats
#define O_D    (O_DCH + 2112)           // 896
#define O_C    (O_D + 896)              // 896
#define O_BETA (O_C + 896)              // 896
#define O_PX2  (O_BETA + 896)           // 896
#define O_PXH  (O_PX2 + 896)            // 896 (half2-dup px2)
#define O_YP   (O_PXH + 896)            // 896
#define O_W2   (O_YP + 896)             // 128
#define O_WX   (O_W2 + 128)             // 512
#define O_BL   (O_WX + 512)             // 512
#define O_SSB  (O_BL + 512)             // 32
#define O_SQ   (O_SSB + 32)             // 8
#define O_WHF  (O_SQ + 8)               // 16384 uint2 = 32768 floats
#define MAIN_FLOATS (O_WHF + 32768)
#define MAIN_SMEM (MAIN_FLOATS * 4)     // ~184 KB

struct Ctx {
    float* sva; float* szp; __half* sdch; float* sd; float* sc; float* sbeta;
    float* spx2; unsigned* spxh; float* syp; float* sW2; float* sWx; float* sbl;
    float* ssb; float* sq; uint2* swhf;
};

// Phase B quarter: one warp per (b, q); 32 timesteps; fp16 window dot
static __device__ __forceinline__ void phaseB(const Ctx& cx, int b0, int b, int q,
                                              int lane, bool last, float b2v)
{
    float4 vr = *(const float4*)(cx.sva + b * SVAS + lane * 4);
    float4 w2r = ((const float4*)cx.sW2)[lane];
    __half2 vr01 = __floats2half2_rn(vr.x, vr.y);
    __half2 vr23 = __floats2half2_rn(vr.z, vr.w);
    __half2 w01  = __floats2half2_rn(w2r.x, w2r.y);
    __half2 w23  = __floats2half2_rn(w2r.z, w2r.w);

    const uint2* pxb = ((const uint2*)(g_prex + (size_t)(b0 + b) * TP * HE)) + lane;
    const unsigned* pxh = cx.spxh + b * 128;
    float s_l = 0.f;
    int tp0 = q * 32;

    uint2 c0 = pxb[(tp0+0)*32], c1 = pxb[(tp0+1)*32];
    uint2 c2 = pxb[(tp0+2)*32], c3 = pxb[(tp0+3)*32];

    #pragma unroll 1
    for (int tc = 0; tc < 32; tc += 4) {
        int tp = tp0 + tc;
        int tn = (tc + 4 < 32) ? tp + 4 : tp;
        uint2 n0 = pxb[(tn+0)*32], n1 = pxb[(tn+1)*32];
        uint2 n2 = pxb[(tn+2)*32], n3 = pxb[(tn+3)*32];

        __half2 h0a = u2h(tanh2_ap(h2u(__hadd2(u2h(c0.x), vr01))));
        __half2 h0b = u2h(tanh2_ap(h2u(__hadd2(u2h(c0.y), vr23))));
        __half2 h1a = u2h(tanh2_ap(h2u(__hadd2(u2h(c1.x), vr01))));
        __half2 h1b = u2h(tanh2_ap(h2u(__hadd2(u2h(c1.y), vr23))));
        __half2 h2a = u2h(tanh2_ap(h2u(__hadd2(u2h(c2.x), vr01))));
        __half2 h2b = u2h(tanh2_ap(h2u(__hadd2(u2h(c2.y), vr23))));
        __half2 h3a = u2h(tanh2_ap(h2u(__hadd2(u2h(c3.x), vr01))));
        __half2 h3b = u2h(tanh2_ap(h2u(__hadd2(u2h(c3.y), vr23))));

        __half2 p0 = __hfma2(h0b, w23, __hmul2(h0a, w01));
        __half2 p1 = __hfma2(h1b, w23, __hmul2(h1a, w01));
        __half2 p2 = __hfma2(h2b, w23, __hmul2(h2a, w01));
        __half2 p3 = __hfma2(h3b, w23, __hmul2(h3a, w01));

        // fp16 window dot with px2 (4 tp), fold to fp32 once per window
        __half2 S2 = __hmul2(p0, u2h(pxh[tp+0]));
        S2 = __hfma2(p1, u2h(pxh[tp+1]), S2);
        S2 = __hfma2(p2, u2h(pxh[tp+2]), S2);
        S2 = __hfma2(p3, u2h(pxh[tp+3]), S2);
        float2 sw = __half22float2(S2);
        s_l += sw.x + sw.y;

        if (last) {
            float2 q0 = __half22float2(p0);
            float2 q1 = __half22float2(p1);
            float2 q2 = __half22float2(p2);
            float2 q3 = __half22float2(p3);
            float r0 = q0.x + q0.y, r1 = q1.x + q1.y;
            float r2 = q2.x + q2.y, r3 = q3.x + q3.y;
            #pragma unroll
            for (int m = 16; m; m >>= 1) {
                r0 += __shfl_xor_sync(0xffffffffu, r0, m);
                r1 += __shfl_xor_sync(0xffffffffu, r1, m);
                r2 += __shfl_xor_sync(0xffffffffu, r2, m);
                r3 += __shfl_xor_sync(0xffffffffu, r3, m);
            }
            if (lane == 0) {
                cx.sbeta[b*128 + tp+0] = r0 + b2v;
                cx.sbeta[b*128 + tp+1] = r1 + b2v;
                cx.sbeta[b*128 + tp+2] = r2 + b2v;
                cx.sbeta[b*128 + tp+3] = r3 + b2v;
            }
        }
        c0 = n0; c1 = n1; c2 = n2; c3 = n3;
    }
    #pragma unroll
    for (int m = 16; m; m >>= 1) s_l += __shfl_xor_sync(0xffffffffu, s_l, m);
    if (lane == 0) cx.ssb[4*b + q] = s_l;
}

__global__ void __launch_bounds__(THREADS, 1)
decoder_kernel(const float* __restrict__ X, const float* __restrict__ yprev,
               const float* __restrict__ W1, const float* __restrict__ W2,
               const float* __restrict__ b2, const float* __restrict__ Wfc,
               const float* __restrict__ bfc, const float* __restrict__ Wx,
               const float* __restrict__ Wh, const float* __restrict__ bl,
               const float* __restrict__ Wf, const float* __restrict__ bf,
               float* __restrict__ out)
{
    extern __shared__ float sm[];
    Ctx cx;
    cx.sva = sm + O_VA;  cx.szp = sm + O_ZP;  cx.sdch = (__half*)(sm + O_DCH);
    cx.sd = sm + O_D;    cx.sc = sm + O_C;    cx.sbeta = sm + O_BETA;
    cx.spx2 = sm + O_PX2; cx.spxh = (unsigned*)(sm + O_PXH);
    cx.syp = sm + O_YP;  cx.sW2 = sm + O_W2;
    cx.sWx = sm + O_WX;  cx.sbl = sm + O_BL;  cx.ssb = sm + O_SSB; cx.sq = sm + O_SQ;
    cx.swhf = (uint2*)(sm + O_WHF);

    int tid = threadIdx.x, lane = tid & 31, wid = tid >> 5;
    int b0 = blockIdx.x * GMAX;
    if (b0 >= BSZ) return;
    int nb = min(GMAX, BSZ - b0);

    if (tid < 128) cx.sW2[tid] = W2[tid];
    if (tid < 512) { cx.sWx[tid] = Wx[tid]; cx.sbl[tid] = bl[tid]; }
    if (tid < 32) cx.ssb[tid] = 0.f;
    if (tid >= 32 && tid < 40) cx.sq[tid - 32] = 0.f;
    for (int i = tid; i < 16 * DCS; i += THREADS) cx.sdch[i] = __float2half(0.f);
    for (int i = tid; i < 16384; i += THREADS) cx.swhf[i] = g_whf[i];
    __syncthreads();
    {
        int b = tid >> 7, k = tid & 127;
        bool ok = (b < nb) && (k < T1);
        float v = ok ? g_px2[(b0 + b) * T1 + k] : 0.f;
        cx.spx2[tid] = v;
        cx.spxh[tid] = h2u(__floats2half2_rn(v, v));
        cx.syp[tid]  = ok ? yprev[(size_t)(b0 + b) * T1 + k] : 0.f;
        float x00 = (b < nb) ? X[(size_t)(b0 + b) * T1 * HE] : 0.f;
        cx.sd[tid] = x00; cx.sc[tid] = x00;
        __half xh = __float2half(x00);
        cx.sdch[b * DCS + k] = xh;
        cx.sdch[b * DCS + 128 + k] = xh;
    }
    float b2v  = b2[0];
    float bfcv = bfc[0];
    float wfcy = Wfc[HE];
    __syncthreads();
    if (wid < nb) {
        const float* p = cx.spx2 + wid * 128;
        float v = p[lane] + p[lane+32] + p[lane+64] + p[lane+96];
        #pragma unroll
        for (int m = 16; m; m >>= 1) v += __shfl_xor_sync(0xffffffffu, v, m);
        if (lane == 0) cx.sq[wid] = v;
    }
    __syncthreads();

    unsigned dch_saddr = (unsigned)__cvta_generic_to_shared(cx.sdch)
                       + (lane % 16) * (DCS * 2) + (lane >> 4) * 16;
    int w = wid - 12;          // mma warps: wid 12..27 -> w 0..15
    int row = lane >> 2;

    for (int t = 0; t < T1; t++) {
        // ---- Region 1 (warps 12-27): A-mma then C-mma ----
        if (w >= 0) {
            {   // A
                uint2 bw[16];
                #pragma unroll
                for (int kt = 0; kt < 16; kt++) bw[kt] = g_w1f[(kt*16 + w)*32 + lane];
                float d0 = 0.f, d1 = 0.f, d2 = 0.f, d3 = 0.f;
                #pragma unroll
                for (int kt = 0; kt < 16; kt++) {
                    unsigned a0, a1, a2, a3;
                    LDSM4(a0, a1, a2, a3, dch_saddr + kt * 32);
                    MMA16816(d0, d1, d2, d3, a0, a1, a2, a3, bw[kt].x, bw[kt].y);
                }
                if (row < GMAX)
                    *(float2*)(cx.sva + row * SVAS + w * 8 + (lane & 3) * 2) = make_float2(d0, d1);
            }
            {   // C (frags from smem)
                float acc[16];
                #pragma unroll
                for (int i = 0; i < 16; i++) acc[i] = 0.f;
                const uint2* whs = cx.swhf + (w * 4) * 32 + lane;
                #pragma unroll
                for (int kt = 0; kt < 8; kt++) {
                    unsigned a0, a1, a2, a3;
                    LDSM4(a0, a1, a2, a3, dch_saddr + kt * 32);
                    uint2 f0 = whs[kt*2048];
                    uint2 f1 = whs[kt*2048 + 32];
                    uint2 f2 = whs[kt*2048 + 64];
                    uint2 f3 = whs[kt*2048 + 96];
                    MMA16816(acc[0],  acc[1],  acc[2],  acc[3],  a0,a1,a2,a3, f0.x, f0.y);
                    MMA16816(acc[4],  acc[5],  acc[6],  acc[7],  a0,a1,a2,a3, f1.x, f1.y);
                    MMA16816(acc[8],  acc[9],  acc[10], acc[11], a0,a1,a2,a3, f2.x, f2.y);
                    MMA16816(acc[12], acc[13], acc[14], acc[15], a0,a1,a2,a3, f3.x, f3.y);
                }
                if (row < GMAX) {
                    float* zb = cx.szp + row * ZPS + w * 32 + (lane & 3) * 2;
                    #pragma unroll
                    for (int nt = 0; nt < 4; nt++)
                        *(float2*)(zb + nt * 8) = make_float2(acc[nt*4], acc[nt*4+1]);
                }
            }
        }
        __syncthreads();

        // ---- Region 2: B on all 28 warps (4 per batch) ----
        {
            bool last = (t == T1 - 1);
            int b = wid >> 2;
            if (b < nb) phaseB(cx, b0, b, wid & 3, lane, last, b2v);
        }
        __syncthreads();

        // ---- Region 3: D — gates, state update (all 896 threads) ----
        {
            int b = tid >> 7, k = tid & 127;
            float s  = cx.ssb[4*b] + cx.ssb[4*b+1] + cx.ssb[4*b+2] + cx.ssb[4*b+3]
                     + b2v * cx.sq[b];
            float yt = fmaf(cx.syp[b*128 + t], wfcy, s + bfcv);
            const float* zb = cx.szp + b * ZPS;
            float zi = fmaf(yt, cx.sWx[k],     zb[k]     + cx.sbl[k]);
            float zf = fmaf(yt, cx.sWx[128+k], zb[128+k] + cx.sbl[128+k]);
            float zg = fmaf(yt, cx.sWx[256+k], zb[256+k] + cx.sbl[256+k]);
            float zo = fmaf(yt, cx.sWx[384+k], zb[384+k] + cx.sbl[384+k]);
            float cn = fmaf(sig_ap(zf), cx.sc[tid], sig_ap(zi) * tanh_ap(zg));
            float dn = sig_ap(zo) * tanh_ap(cn);
            cx.sc[tid] = cn;
            cx.sd[tid] = dn;
            cx.sdch[b * DCS + k]       = __float2half(dn);
            cx.sdch[b * DCS + 128 + k] = __float2half(cn);
        }
        __syncthreads();
    }

    // ---- Epilogue ----
    if (wid < nb) {
        int b = wid;
        const float4* Xb = (const float4*)(X + (size_t)(b0 + b) * T1 * HE);
        float cxx = 0.f, cy = 0.f, cz = 0.f, cw = 0.f;
        for (int tp = 0; tp < T1; tp++) {
            float bb = cx.sbeta[b*128 + tp];
            float4 xv = Xb[tp*32 + lane];
            cxx = fmaf(bb, xv.x, cxx); cy = fmaf(bb, xv.y, cy);
            cz  = fmaf(bb, xv.z, cz);  cw = fmaf(bb, xv.w, cw);
        }
        float4 wfc2 = ((const float4*)(Wf + 128))[lane];
        float4 wfd  = ((const float4*)Wf)[lane];
        float4 dv   = ((const float4*)(cx.sd + b*128))[lane];
        float r = cxx*wfc2.x + cy*wfc2.y + cz*wfc2.z + cw*wfc2.w;
        r = fmaf(dv.x, wfd.x, r); r = fmaf(dv.y, wfd.y, r);
        r = fmaf(dv.z, wfd.z, r); r = fmaf(dv.w, wfd.w, r);
        #pragma unroll
        for (int m = 16; m; m >>= 1) r += __shfl_xor_sync(0xffffffffu, r, m);
        if (lane == 0) out[b0 + b] = r + bf[0];
    }
}

extern "C" void kernel_launch(void* const* d_in, const int* in_sizes, int n_in,
                              void* d_out, int out_size)
{
    const float* X    = (const float*)d_in[0];
    const float* yprev= (const float*)d_in[1];
    const float* W1   = (const float*)d_in[2];
    const float* b1   = (const float*)d_in[3];
    const float* W2   = (const float*)d_in[4];
    const float* b2   = (const float*)d_in[5];
    const float* Wfc  = (const float*)d_in[6];
    const float* bfc  = (const float*)d_in[7];
    const float* Wx   = (const float*)d_in[8];
    const float* Wh   = (const float*)d_in[9];
    const float* bl   = (const float*)d_in[10];
    const float* Wf   = (const float*)d_in[11];
    const float* bf   = (const float*)d_in[12];
    float* out = (float*)d_out;

    cudaFuncSetAttribute(decoder_kernel, cudaFuncAttributeMaxDynamicSharedMemorySize, MAIN_SMEM);

    pack_kernel<<<112, 256>>>(W1, Wh);
    prex_kernel<<<BSZ, 256>>>(X, b1, Wfc);
    decoder_kernel<<<NCTA, THREADS, MAIN_SMEM>>>(X, yprev, W1, W2, b2, Wfc, bfc,
                                                 Wx, Wh, bl, Wf, bf, out);
}